// round 2
// baseline (speedup 1.0000x reference)
#include <cuda_runtime.h>

// Problem constants
#define B_SZ   4
#define C_LEN  2048
#define H_N    8
#define DK_    64
#define DV_    128
#define DIN_   1024

#define QK_COLS (H_N * DK_)   // 512
#define V_COLS  (H_N * DV_)   // 1024
#define M_ROWS  (B_SZ * C_LEN) // 8192

// Scratch (device globals: allocation-free per harness rules)
__device__ __align__(16) float g_q[B_SZ * C_LEN * QK_COLS];             // 16 MB
__device__ __align__(16) float g_k[B_SZ * C_LEN * QK_COLS];             // 16 MB
__device__ __align__(16) float g_v[B_SZ * C_LEN * V_COLS];              // 32 MB
__device__ __align__(16) float g_s[(size_t)B_SZ * H_N * C_LEN * C_LEN]; // 512 MB
__device__ __align__(16) float g_ao[B_SZ * C_LEN * V_COLS];             // 32 MB

// ---------------------------------------------------------------------------
// Generic NT SGEMM:  C[M,N] = A[M,K] @ W[N,K]^T + bias[N]
// 128x128 tile, BK=8, 256 threads, 8x8 register tile per thread.
// ---------------------------------------------------------------------------
__global__ void __launch_bounds__(256) gemm_nt_bias(
    const float* __restrict__ A, const float* __restrict__ W,
    const float* __restrict__ bias, float* __restrict__ C,
    int M, int N, int K)
{
    __shared__ float As[8][132];
    __shared__ float Bs[8][132];

    const int tid = threadIdx.x;
    const int bm = blockIdx.y * 128;
    const int bn = blockIdx.x * 128;

    const int lrow = tid >> 1;          // 0..127
    const int lcol = (tid & 1) * 4;     // 0 or 4
    const int tx = tid & 15;
    const int ty = tid >> 4;

    const float* Aptr = A + (size_t)(bm + lrow) * K + lcol;
    const float* Wptr = W + (size_t)(bn + lrow) * K + lcol;

    float acc[8][8];
    #pragma unroll
    for (int i = 0; i < 8; i++)
        #pragma unroll
        for (int j = 0; j < 8; j++) acc[i][j] = 0.f;

    for (int k0 = 0; k0 < K; k0 += 8) {
        float4 av = *(const float4*)(Aptr + k0);
        float4 wv = *(const float4*)(Wptr + k0);
        As[lcol + 0][lrow] = av.x; As[lcol + 1][lrow] = av.y;
        As[lcol + 2][lrow] = av.z; As[lcol + 3][lrow] = av.w;
        Bs[lcol + 0][lrow] = wv.x; Bs[lcol + 1][lrow] = wv.y;
        Bs[lcol + 2][lrow] = wv.z; Bs[lcol + 3][lrow] = wv.w;
        __syncthreads();
        #pragma unroll
        for (int kk = 0; kk < 8; kk++) {
            float a[8], b[8];
            *(float4*)(a)     = *(const float4*)&As[kk][ty * 8];
            *(float4*)(a + 4) = *(const float4*)&As[kk][ty * 8 + 4];
            *(float4*)(b)     = *(const float4*)&Bs[kk][tx * 8];
            *(float4*)(b + 4) = *(const float4*)&Bs[kk][tx * 8 + 4];
            #pragma unroll
            for (int i = 0; i < 8; i++)
                #pragma unroll
                for (int j = 0; j < 8; j++)
                    acc[i][j] += a[i] * b[j];
        }
        __syncthreads();
    }

    #pragma unroll
    for (int i = 0; i < 8; i++) {
        const int row = bm + ty * 8 + i;
        #pragma unroll
        for (int j = 0; j < 8; j += 4) {
            const int col = bn + tx * 8 + j;
            float4 o;
            o.x = acc[i][j]     + bias[col];
            o.y = acc[i][j + 1] + bias[col + 1];
            o.z = acc[i][j + 2] + bias[col + 2];
            o.w = acc[i][j + 3] + bias[col + 3];
            *(float4*)(C + (size_t)row * N + col) = o;
        }
    }
}

// ---------------------------------------------------------------------------
// Batched scores: S_z[q,k] = (Q_z[q,:] . K_z[k,:] + mask[b,q]) / 8
// z = b*H + h; Q_z/K_z are contiguous [2048,64] slices; S_z is [2048,2048].
// grid (16, 16, 32)
// ---------------------------------------------------------------------------
__global__ void __launch_bounds__(256) gemm_scores(
    const float* __restrict__ Q, const float* __restrict__ Kk,
    const float* __restrict__ mask)
{
    __shared__ float As[8][132];
    __shared__ float Bs[8][132];

    const int z = blockIdx.z;
    const float* A = Q  + (size_t)z * (C_LEN * DK_);
    const float* W = Kk + (size_t)z * (C_LEN * DK_);
    float* Cc = g_s + (size_t)z * ((size_t)C_LEN * C_LEN);
    const float* mrow = mask + (z >> 3) * C_LEN;

    const int tid = threadIdx.x;
    const int bm = blockIdx.y * 128;
    const int bn = blockIdx.x * 128;
    const int lrow = tid >> 1;
    const int lcol = (tid & 1) * 4;
    const int tx = tid & 15;
    const int ty = tid >> 4;

    const float* Aptr = A + (size_t)(bm + lrow) * DK_ + lcol;
    const float* Wptr = W + (size_t)(bn + lrow) * DK_ + lcol;

    float acc[8][8];
    #pragma unroll
    for (int i = 0; i < 8; i++)
        #pragma unroll
        for (int j = 0; j < 8; j++) acc[i][j] = 0.f;

    #pragma unroll
    for (int k0 = 0; k0 < DK_; k0 += 8) {
        float4 av = *(const float4*)(Aptr + k0);
        float4 wv = *(const float4*)(Wptr + k0);
        As[lcol + 0][lrow] = av.x; As[lcol + 1][lrow] = av.y;
        As[lcol + 2][lrow] = av.z; As[lcol + 3][lrow] = av.w;
        Bs[lcol + 0][lrow] = wv.x; Bs[lcol + 1][lrow] = wv.y;
        Bs[lcol + 2][lrow] = wv.z; Bs[lcol + 3][lrow] = wv.w;
        __syncthreads();
        #pragma unroll
        for (int kk = 0; kk < 8; kk++) {
            float a[8], b[8];
            *(float4*)(a)     = *(const float4*)&As[kk][ty * 8];
            *(float4*)(a + 4) = *(const float4*)&As[kk][ty * 8 + 4];
            *(float4*)(b)     = *(const float4*)&Bs[kk][tx * 8];
            *(float4*)(b + 4) = *(const float4*)&Bs[kk][tx * 8 + 4];
            #pragma unroll
            for (int i = 0; i < 8; i++)
                #pragma unroll
                for (int j = 0; j < 8; j++)
                    acc[i][j] += a[i] * b[j];
        }
        __syncthreads();
    }

    #pragma unroll
    for (int i = 0; i < 8; i++) {
        const int row = bm + ty * 8 + i;
        const float mv = mrow[row];
        #pragma unroll
        for (int j = 0; j < 8; j += 4) {
            const int col = bn + tx * 8 + j;
            float4 o;
            o.x = (acc[i][j]     + mv) * 0.125f;
            o.y = (acc[i][j + 1] + mv) * 0.125f;
            o.z = (acc[i][j + 2] + mv) * 0.125f;
            o.w = (acc[i][j + 3] + mv) * 0.125f;
            *(float4*)(Cc + (size_t)row * C_LEN + col) = o;
        }
    }
}

// ---------------------------------------------------------------------------
// Column softmax (over the QUERY axis, per reference): for each (z, col):
//   P[q,col] = exp(S[q,col]-m) / sum_q exp(S[q,col]-m)
// grid (8, 32), 256 threads; one thread per column, coalesced across threads.
// ---------------------------------------------------------------------------
__global__ void __launch_bounds__(256) softmax_col()
{
    const int z = blockIdx.y;
    const int col = blockIdx.x * 256 + threadIdx.x;
    float* base = g_s + (size_t)z * ((size_t)C_LEN * C_LEN) + col;

    float m = -1e30f;
    #pragma unroll 8
    for (int q = 0; q < C_LEN; q++)
        m = fmaxf(m, base[(size_t)q * C_LEN]);

    float sum = 0.f;
    #pragma unroll 8
    for (int q = 0; q < C_LEN; q++)
        sum += __expf(base[(size_t)q * C_LEN] - m);

    const float inv = 1.0f / sum;
    #pragma unroll 8
    for (int q = 0; q < C_LEN; q++) {
        float vv = __expf(base[(size_t)q * C_LEN] - m) * inv;
        base[(size_t)q * C_LEN] = vv;
    }
}

// ---------------------------------------------------------------------------
// Batched NN GEMM: AO_z[q,d] = P_z[q,:] @ V_z[:,d]
// P_z: [2048,2048] row-major; V_z: [2048,128] row-major; AO_z: [2048,128].
// grid (16, 32): x = M-tile, y = z. Full N (128) in one block column.
// ---------------------------------------------------------------------------
__global__ void __launch_bounds__(256) gemm_av()
{
    __shared__ float As[8][132];
    __shared__ float Bs[8][132];

    const int z = blockIdx.y;
    const float* A = g_s + (size_t)z * ((size_t)C_LEN * C_LEN);
    const float* V = g_v + (size_t)z * (C_LEN * DV_);
    float* Cc = g_ao + (size_t)z * (C_LEN * DV_);

    const int tid = threadIdx.x;
    const int bm = blockIdx.x * 128;
    const int lrow = tid >> 1;
    const int lcol = (tid & 1) * 4;
    const int brow = tid >> 5;          // 0..7
    const int bcol = (tid & 31) * 4;    // 0..124
    const int tx = tid & 15;
    const int ty = tid >> 4;

    const float* Aptr = A + (size_t)(bm + lrow) * C_LEN + lcol;

    float acc[8][8];
    #pragma unroll
    for (int i = 0; i < 8; i++)
        #pragma unroll
        for (int j = 0; j < 8; j++) acc[i][j] = 0.f;

    for (int k0 = 0; k0 < C_LEN; k0 += 8) {
        float4 av = *(const float4*)(Aptr + k0);
        float4 vv = *(const float4*)(V + (size_t)(k0 + brow) * DV_ + bcol);
        As[lcol + 0][lrow] = av.x; As[lcol + 1][lrow] = av.y;
        As[lcol + 2][lrow] = av.z; As[lcol + 3][lrow] = av.w;
        *(float4*)&Bs[brow][bcol] = vv;
        __syncthreads();
        #pragma unroll
        for (int kk = 0; kk < 8; kk++) {
            float a[8], b[8];
            *(float4*)(a)     = *(const float4*)&As[kk][ty * 8];
            *(float4*)(a + 4) = *(const float4*)&As[kk][ty * 8 + 4];
            *(float4*)(b)     = *(const float4*)&Bs[kk][tx * 8];
            *(float4*)(b + 4) = *(const float4*)&Bs[kk][tx * 8 + 4];
            #pragma unroll
            for (int i = 0; i < 8; i++)
                #pragma unroll
                for (int j = 0; j < 8; j++)
                    acc[i][j] += a[i] * b[j];
        }
        __syncthreads();
    }

    #pragma unroll
    for (int i = 0; i < 8; i++) {
        const int row = bm + ty * 8 + i;
        #pragma unroll
        for (int j = 0; j < 8; j += 4) {
            const int col = tx * 8 + j;
            float4 o;
            o.x = acc[i][j];
            o.y = acc[i][j + 1];
            o.z = acc[i][j + 2];
            o.w = acc[i][j + 3];
            *(float4*)(Cc + (size_t)row * DV_ + col) = o;
        }
    }
}

// ---------------------------------------------------------------------------
extern "C" void kernel_launch(void* const* d_in, const int* in_sizes, int n_in,
                              void* d_out, int out_size)
{
    const float* x    = (const float*)d_in[0];
    const float* mask = (const float*)d_in[1];
    const float* Mq_w = (const float*)d_in[2];
    const float* Mq_b = (const float*)d_in[3];
    const float* Mk_w = (const float*)d_in[4];
    const float* Mk_b = (const float*)d_in[5];
    const float* Mv_w = (const float*)d_in[6];
    const float* Mv_b = (const float*)d_in[7];
    const float* Wo_w = (const float*)d_in[8];
    const float* Wo_b = (const float*)d_in[9];
    float* out = (float*)d_out;

    float *q, *k, *v, *ao;
    cudaGetSymbolAddress((void**)&q,  g_q);
    cudaGetSymbolAddress((void**)&k,  g_k);
    cudaGetSymbolAddress((void**)&v,  g_v);
    cudaGetSymbolAddress((void**)&ao, g_ao);

    dim3 blk(256);

    // QKV projections: [8192,1024] @ [Nout,1024]^T + b
    gemm_nt_bias<<<dim3(QK_COLS / 128, M_ROWS / 128), blk>>>(x, Mq_w, Mq_b, q, M_ROWS, QK_COLS, DIN_);
    gemm_nt_bias<<<dim3(QK_COLS / 128, M_ROWS / 128), blk>>>(x, Mk_w, Mk_b, k, M_ROWS, QK_COLS, DIN_);
    gemm_nt_bias<<<dim3(V_COLS / 128,  M_ROWS / 128), blk>>>(x, Mv_w, Mv_b, v, M_ROWS, V_COLS, DIN_);

    // S = (Q K^T + mask) / sqrt(dk), batched over z = b*H + h
    gemm_scores<<<dim3(C_LEN / 128, C_LEN / 128, B_SZ * H_N), blk>>>(q, k, mask);

    // Softmax over query axis (columns of S)
    softmax_col<<<dim3(C_LEN / 256, B_SZ * H_N), blk>>>();

    // AO = P @ V, batched
    gemm_av<<<dim3(C_LEN / 128, B_SZ * H_N), blk>>>();

    // Output projection: [8192,1024] @ [1024,1024]^T + b -> d_out
    gemm_nt_bias<<<dim3(V_COLS / 128, M_ROWS / 128), blk>>>(ao, Wo_w, Wo_b, out, M_ROWS, V_COLS, DIN_);
}

// round 4
// speedup vs baseline: 1.3563x; 1.3563x over previous
#include <cuda_runtime.h>
#include <cuda_bf16.h>
#include <cstdint>

#define B_SZ   4
#define C_LEN  2048
#define H_N    8
#define DK_    64
#define DV_    128
#define DIN_   1024
#define QK_COLS 512
#define V_COLS  1024
#define M_ROWS  8192
#define NZ      32

typedef unsigned int u32;
typedef unsigned short u16;

// ----------------------- device scratch (no allocs) -----------------------
__device__ __align__(16) __nv_bfloat16 g_xs_h[M_ROWS * DIN_];
__device__ __align__(16) __nv_bfloat16 g_xs_l[M_ROWS * DIN_];
__device__ __align__(16) __nv_bfloat16 g_wq_h[QK_COLS * DIN_];
__device__ __align__(16) __nv_bfloat16 g_wq_l[QK_COLS * DIN_];
__device__ __align__(16) __nv_bfloat16 g_wk_h[QK_COLS * DIN_];
__device__ __align__(16) __nv_bfloat16 g_wk_l[QK_COLS * DIN_];
__device__ __align__(16) __nv_bfloat16 g_wv_h[V_COLS * DIN_];
__device__ __align__(16) __nv_bfloat16 g_wv_l[V_COLS * DIN_];
__device__ __align__(16) __nv_bfloat16 g_wo_h[V_COLS * V_COLS];
__device__ __align__(16) __nv_bfloat16 g_wo_l[V_COLS * V_COLS];
__device__ __align__(16) __nv_bfloat16 g_q_h[M_ROWS * QK_COLS];
__device__ __align__(16) __nv_bfloat16 g_q_l[M_ROWS * QK_COLS];
__device__ __align__(16) __nv_bfloat16 g_k_h[M_ROWS * QK_COLS];
__device__ __align__(16) __nv_bfloat16 g_k_l[M_ROWS * QK_COLS];
__device__ __align__(16) __nv_bfloat16 g_e_h[(size_t)NZ * C_LEN * C_LEN]; // 256MB
__device__ __align__(16) __nv_bfloat16 g_e_l[(size_t)NZ * C_LEN * C_LEN]; // 256MB
__device__ __align__(16) float         g_v [M_ROWS * V_COLS];             // 32MB
__device__ __align__(16) __nv_bfloat16 g_vt_h[M_ROWS * V_COLS];
__device__ __align__(16) __nv_bfloat16 g_vt_l[M_ROWS * V_COLS];
__device__ __align__(16) __nv_bfloat16 g_ao_h[M_ROWS * V_COLS];
__device__ __align__(16) __nv_bfloat16 g_ao_l[M_ROWS * V_COLS];
__device__ __align__(16) float         g_inv[NZ * C_LEN];

// ----------------------- helpers -----------------------
__device__ __forceinline__ u32 smem_u32(const void* p) {
    return (u32)__cvta_generic_to_shared(p);
}
__device__ __forceinline__ void ldsm4(u32& r0, u32& r1, u32& r2, u32& r3, u32 a) {
    asm volatile("ldmatrix.sync.aligned.m8n8.x4.shared.b16 {%0,%1,%2,%3}, [%4];\n"
                 : "=r"(r0), "=r"(r1), "=r"(r2), "=r"(r3) : "r"(a));
}
__device__ __forceinline__ void mma16816(float* d, const u32* a, u32 b0, u32 b1) {
    asm volatile(
        "mma.sync.aligned.m16n8k16.row.col.f32.bf16.bf16.f32 "
        "{%0,%1,%2,%3},{%4,%5,%6,%7},{%8,%9},{%0,%1,%2,%3};\n"
        : "+f"(d[0]), "+f"(d[1]), "+f"(d[2]), "+f"(d[3])
        : "r"(a[0]), "r"(a[1]), "r"(a[2]), "r"(a[3]), "r"(b0), "r"(b1));
}
// split (a,b) -> packed bf16x2 hi and lo
__device__ __forceinline__ void pack_split(float a, float b, u32& hi, u32& lo) {
    __nv_bfloat16 ha = __float2bfloat16_rn(a), hb = __float2bfloat16_rn(b);
    __nv_bfloat16 la = __float2bfloat16_rn(a - __bfloat162float(ha));
    __nv_bfloat16 lb = __float2bfloat16_rn(b - __bfloat162float(hb));
    __nv_bfloat162 hp; hp.x = ha; hp.y = hb;
    __nv_bfloat162 lp; lp.x = la; lp.y = lb;
    hi = *(u32*)&hp; lo = *(u32*)&lp;
}

// ----------------------- fp32 -> bf16 hi/lo split -----------------------
__global__ void __launch_bounds__(256) split_f32(
    const float* __restrict__ src, __nv_bfloat16* __restrict__ h,
    __nv_bfloat16* __restrict__ l, int n4)
{
    int i = blockIdx.x * 256 + threadIdx.x;
    if (i >= n4) return;
    float4 v = ((const float4*)src)[i];
    u32 h0, l0, h1, l1;
    pack_split(v.x, v.y, h0, l0);
    pack_split(v.z, v.w, h1, l1);
    uint2 hh; hh.x = h0; hh.y = h1;
    uint2 ll; ll.x = l0; ll.y = l1;
    ((uint2*)h)[i] = hh;
    ((uint2*)l)[i] = ll;
}

// ---------------------------------------------------------------------------
// bf16 3-term NT GEMM: C = A@B^T (+bias)(+epilogue), acc = AhBh + AlBh + AhBl
// BM=128, BN=64, BK=16. 256 thr, warps 4(m) x 2(n), warp tile 32x32, m16n8k16.
// MODE 0: fp32 out + bias. MODE 1: split bf16 out (+bias if non-null).
// MODE 2: E = exp((acc + mask[q]) * 0.125) -> split bf16 out.
// ---------------------------------------------------------------------------
template <int MODE>
__global__ void __launch_bounds__(256) gemm_bf3(
    const __nv_bfloat16* __restrict__ Ah, const __nv_bfloat16* __restrict__ Al,
    const __nv_bfloat16* __restrict__ Bh, const __nv_bfloat16* __restrict__ Bl,
    const float* __restrict__ bias, const float* __restrict__ mask,
    float* __restrict__ Cf,
    __nv_bfloat16* __restrict__ Ch, __nv_bfloat16* __restrict__ Cl,
    int K, int lda, int ldb, int ldc,
    size_t sA, size_t sB, size_t sC)
{
    __shared__ __align__(16) u16 As[128 * 24];
    __shared__ __align__(16) u16 Bs[64 * 24];

    const int tid = threadIdx.x;
    const int lane = tid & 31, wid = tid >> 5;
    const int wm = wid & 3, wn = wid >> 2;
    const int bm = blockIdx.y * 128, bn = blockIdx.x * 64;
    const int z = blockIdx.z;

    Ah += sA * z; Al += sA * z; Bh += sB * z; Bl += sB * z;
    // batched output offset (bug fixed in R4: apply for ALL modes)
    if (Cf) Cf += sC * z;
    if (Ch) { Ch += sC * z; Cl += sC * z; }

    // gmem staging offsets
    const int ar = tid >> 1, ac = (tid & 1) * 8;     // A: 128 rows x 16B
    const int br = tid >> 2, bc = (tid & 3) * 4;     // B: 64 rows x 8B
    const size_t aoff = (size_t)(bm + ar) * lda + ac;
    const size_t boff = (size_t)(bn + br) * ldb + bc;

    // ldmatrix addresses (fixed per lane)
    const int grp = lane >> 3, l8 = lane & 7;
    const int amr = ((grp & 1) << 3) + l8, amc = (grp >> 1) << 3;
    const int bmr = ((grp >> 1) << 3) + l8, bmc = (grp & 1) << 3;
    u32 a_addr[2], b_addr[2];
#pragma unroll
    for (int mi = 0; mi < 2; mi++)
        a_addr[mi] = smem_u32(&As[(wm * 32 + mi * 16 + amr) * 24 + amc]);
#pragma unroll
    for (int p = 0; p < 2; p++)
        b_addr[p] = smem_u32(&Bs[(wn * 32 + p * 16 + bmr) * 24 + bmc]);

    float acc[2][4][4] = {};

    const int KD16 = K >> 4;
    const int NIT = 3 * KD16;
    uint4 pa; uint2 pb;

    auto gload = [&](int it) {
        int pass = it / KD16;
        int k0 = (it - pass * KD16) << 4;
        const __nv_bfloat16* Ap = (pass == 1) ? Al : Ah;
        const __nv_bfloat16* Bp = (pass == 2) ? Bl : Bh;
        pa = *(const uint4*)(Ap + aoff + k0);
        pb = *(const uint2*)(Bp + boff + k0);
    };

    gload(0);
    for (int it = 0; it < NIT; ++it) {
        __syncthreads();
        *(uint4*)&As[ar * 24 + ac] = pa;
        *(uint2*)&Bs[br * 24 + bc] = pb;
        __syncthreads();
        if (it + 1 < NIT) gload(it + 1);

        u32 af[2][4], bf[2][4];
        ldsm4(af[0][0], af[0][1], af[0][2], af[0][3], a_addr[0]);
        ldsm4(af[1][0], af[1][1], af[1][2], af[1][3], a_addr[1]);
        ldsm4(bf[0][0], bf[0][1], bf[0][2], bf[0][3], b_addr[0]);
        ldsm4(bf[1][0], bf[1][1], bf[1][2], bf[1][3], b_addr[1]);
#pragma unroll
        for (int mi = 0; mi < 2; mi++)
#pragma unroll
            for (int ni = 0; ni < 4; ni++)
                mma16816(acc[mi][ni], af[mi],
                         bf[ni >> 1][(ni & 1) * 2], bf[ni >> 1][(ni & 1) * 2 + 1]);
    }

    // epilogue
    const int lr = lane >> 2, lc2 = (lane & 3) * 2;
#pragma unroll
    for (int mi = 0; mi < 2; mi++) {
        const int m0 = bm + wm * 32 + mi * 16 + lr;
        float mk0 = 0.f, mk8 = 0.f;
        if (MODE == 2) {
            const float* mrow = mask + (size_t)(z >> 3) * C_LEN;
            mk0 = mrow[m0]; mk8 = mrow[m0 + 8];
        }
#pragma unroll
        for (int ni = 0; ni < 4; ni++) {
            const int n0 = bn + wn * 32 + ni * 8 + lc2;
            float c0 = acc[mi][ni][0], c1 = acc[mi][ni][1];
            float c2 = acc[mi][ni][2], c3 = acc[mi][ni][3];
            if (MODE == 0) {
                float b0 = bias[n0], b1 = bias[n0 + 1];
                float2 r0; r0.x = c0 + b0; r0.y = c1 + b1;
                float2 r1; r1.x = c2 + b0; r1.y = c3 + b1;
                *(float2*)(Cf + (size_t)m0 * ldc + n0) = r0;
                *(float2*)(Cf + (size_t)(m0 + 8) * ldc + n0) = r1;
            } else if (MODE == 1) {
                float b0 = 0.f, b1 = 0.f;
                if (bias) { b0 = bias[n0]; b1 = bias[n0 + 1]; }
                u32 h0, l0, h1, l1;
                pack_split(c0 + b0, c1 + b1, h0, l0);
                pack_split(c2 + b0, c3 + b1, h1, l1);
                *(u32*)(Ch + (size_t)m0 * ldc + n0) = h0;
                *(u32*)(Cl + (size_t)m0 * ldc + n0) = l0;
                *(u32*)(Ch + (size_t)(m0 + 8) * ldc + n0) = h1;
                *(u32*)(Cl + (size_t)(m0 + 8) * ldc + n0) = l1;
            } else { // MODE 2
                float e0 = __expf((c0 + mk0) * 0.125f);
                float e1 = __expf((c1 + mk0) * 0.125f);
                float e2 = __expf((c2 + mk8) * 0.125f);
                float e3 = __expf((c3 + mk8) * 0.125f);
                u32 h0, l0, h1, l1;
                pack_split(e0, e1, h0, l0);
                pack_split(e2, e3, h1, l1);
                *(u32*)(Ch + (size_t)m0 * ldc + n0) = h0;
                *(u32*)(Cl + (size_t)m0 * ldc + n0) = l0;
                *(u32*)(Ch + (size_t)(m0 + 8) * ldc + n0) = h1;
                *(u32*)(Cl + (size_t)(m0 + 8) * ldc + n0) = l1;
            }
        }
    }
}

// ----------------------- column sums over q: inv[z][k] = 1/sum_q E -----------------------
__global__ void __launch_bounds__(256) colsum_k()
{
    const int z = blockIdx.y;
    const int k = blockIdx.x * 256 + threadIdx.x;
    const size_t base = (size_t)z * C_LEN * C_LEN + k;
    float s = 0.f;
#pragma unroll 8
    for (int q = 0; q < C_LEN; q++) {
        size_t idx = base + (size_t)q * C_LEN;
        s += __bfloat162float(g_e_h[idx]) + __bfloat162float(g_e_l[idx]);
    }
    g_inv[z * C_LEN + k] = 1.0f / s;
}

// ----------------------- V' transpose+scale: vt[z][d][k] = inv[z][k]*V[z][k][d] -----------------------
__global__ void __launch_bounds__(256) scale_v()
{
    __shared__ float t[32][33];
    const int z = blockIdx.z;
    const int k0 = blockIdx.x * 32, d0 = blockIdx.y * 32;
    const int tx = threadIdx.x & 31, ty = threadIdx.x >> 5; // 32 x 8
    const size_t vbase = (size_t)z * (C_LEN * DV_);
#pragma unroll
    for (int i = 0; i < 4; i++)
        t[ty + i * 8][tx] = g_v[vbase + (size_t)(k0 + ty + i * 8) * DV_ + d0 + tx];
    __syncthreads();
    const float iv = g_inv[z * C_LEN + k0 + tx];
#pragma unroll
    for (int i = 0; i < 4; i++) {
        float val = t[tx][ty + i * 8] * iv;
        __nv_bfloat16 h = __float2bfloat16_rn(val);
        __nv_bfloat16 l = __float2bfloat16_rn(val - __bfloat162float(h));
        size_t o = vbase + (size_t)(d0 + ty + i * 8) * C_LEN + k0 + tx;
        g_vt_h[o] = h;
        g_vt_l[o] = l;
    }
}

// ---------------------------------------------------------------------------
extern "C" void kernel_launch(void* const* d_in, const int* in_sizes, int n_in,
                              void* d_out, int out_size)
{
    const float* x    = (const float*)d_in[0];
    const float* mask = (const float*)d_in[1];
    const float* Mq_w = (const float*)d_in[2];
    const float* Mq_b = (const float*)d_in[3];
    const float* Mk_w = (const float*)d_in[4];
    const float* Mk_b = (const float*)d_in[5];
    const float* Mv_w = (const float*)d_in[6];
    const float* Mv_b = (const float*)d_in[7];
    const float* Wo_w = (const float*)d_in[8];
    const float* Wo_b = (const float*)d_in[9];
    float* out = (float*)d_out;

    __nv_bfloat16 *xs_h, *xs_l, *wq_h, *wq_l, *wk_h, *wk_l, *wv_h, *wv_l;
    __nv_bfloat16 *wo_h, *wo_l, *q_h, *q_l, *k_h, *k_l, *e_h, *e_l;
    __nv_bfloat16 *vt_h, *vt_l, *ao_h, *ao_l;
    float *v;
    cudaGetSymbolAddress((void**)&xs_h, g_xs_h); cudaGetSymbolAddress((void**)&xs_l, g_xs_l);
    cudaGetSymbolAddress((void**)&wq_h, g_wq_h); cudaGetSymbolAddress((void**)&wq_l, g_wq_l);
    cudaGetSymbolAddress((void**)&wk_h, g_wk_h); cudaGetSymbolAddress((void**)&wk_l, g_wk_l);
    cudaGetSymbolAddress((void**)&wv_h, g_wv_h); cudaGetSymbolAddress((void**)&wv_l, g_wv_l);
    cudaGetSymbolAddress((void**)&wo_h, g_wo_h); cudaGetSymbolAddress((void**)&wo_l, g_wo_l);
    cudaGetSymbolAddress((void**)&q_h,  g_q_h);  cudaGetSymbolAddress((void**)&q_l,  g_q_l);
    cudaGetSymbolAddress((void**)&k_h,  g_k_h);  cudaGetSymbolAddress((void**)&k_l,  g_k_l);
    cudaGetSymbolAddress((void**)&e_h,  g_e_h);  cudaGetSymbolAddress((void**)&e_l,  g_e_l);
    cudaGetSymbolAddress((void**)&vt_h, g_vt_h); cudaGetSymbolAddress((void**)&vt_l, g_vt_l);
    cudaGetSymbolAddress((void**)&ao_h, g_ao_h); cudaGetSymbolAddress((void**)&ao_l, g_ao_l);
    cudaGetSymbolAddress((void**)&v,    g_v);

    dim3 blk(256);

    // splits
    split_f32<<<(M_ROWS * DIN_ / 4 + 255) / 256, blk>>>(x, xs_h, xs_l, M_ROWS * DIN_ / 4);
    split_f32<<<(QK_COLS * DIN_ / 4 + 255) / 256, blk>>>(Mq_w, wq_h, wq_l, QK_COLS * DIN_ / 4);
    split_f32<<<(QK_COLS * DIN_ / 4 + 255) / 256, blk>>>(Mk_w, wk_h, wk_l, QK_COLS * DIN_ / 4);
    split_f32<<<(V_COLS * DIN_ / 4 + 255) / 256, blk>>>(Mv_w, wv_h, wv_l, V_COLS * DIN_ / 4);
    split_f32<<<(V_COLS * V_COLS / 4 + 255) / 256, blk>>>(Wo_w, wo_h, wo_l, V_COLS * V_COLS / 4);

    // Q, K projections -> split bf16 outputs
    gemm_bf3<1><<<dim3(QK_COLS / 64, M_ROWS / 128, 1), blk>>>(
        xs_h, xs_l, wq_h, wq_l, Mq_b, nullptr, nullptr, q_h, q_l,
        DIN_, DIN_, DIN_, QK_COLS, 0, 0, 0);
    gemm_bf3<1><<<dim3(QK_COLS / 64, M_ROWS / 128, 1), blk>>>(
        xs_h, xs_l, wk_h, wk_l, Mk_b, nullptr, nullptr, k_h, k_l,
        DIN_, DIN_, DIN_, QK_COLS, 0, 0, 0);
    // V projection -> fp32
    gemm_bf3<0><<<dim3(V_COLS / 64, M_ROWS / 128, 1), blk>>>(
        xs_h, xs_l, wv_h, wv_l, Mv_b, nullptr, v, nullptr, nullptr,
        DIN_, DIN_, DIN_, V_COLS, 0, 0, 0);

    // scores -> E = exp((QK^T + mask)/8), split bf16, batched over z
    gemm_bf3<2><<<dim3(C_LEN / 64, C_LEN / 128, NZ), blk>>>(
        q_h, q_l, k_h, k_l, nullptr, mask, nullptr, e_h, e_l,
        DK_, DK_, DK_, C_LEN,
        (size_t)C_LEN * DK_, (size_t)C_LEN * DK_, (size_t)C_LEN * C_LEN);

    // per-key-column inverse sums over q
    colsum_k<<<dim3(C_LEN / 256, NZ), blk>>>();

    // V' = inv * V, transposed to [z][d][k], split bf16
    scale_v<<<dim3(C_LEN / 32, DV_ / 32, NZ), blk>>>();

    // AO = E @ V'^T (NT with B rows = d), split bf16 out, contiguous [z][q][d]
    gemm_bf3<1><<<dim3(DV_ / 64, C_LEN / 128, NZ), blk>>>(
        e_h, e_l, vt_h, vt_l, nullptr, nullptr, nullptr, ao_h, ao_l,
        C_LEN, C_LEN, C_LEN, DV_,
        (size_t)C_LEN * C_LEN, (size_t)C_LEN * DV_, (size_t)C_LEN * DV_);

    // out projection -> d_out fp32
    gemm_bf3<0><<<dim3(V_COLS / 64, M_ROWS / 128, 1), blk>>>(
        ao_h, ao_l, wo_h, wo_l, Wo_b, nullptr, out, nullptr, nullptr,
        V_COLS, V_COLS, V_COLS, V_COLS, 0, 0, 0);
}

// round 5
// speedup vs baseline: 2.4360x; 1.7961x over previous
#include <cuda_runtime.h>
#include <cuda_bf16.h>
#include <cstdint>

#define B_SZ   4
#define C_LEN  2048
#define H_N    8
#define DK_    64
#define DV_    128
#define DIN_   1024
#define QK_COLS 512
#define V_COLS  1024
#define M_ROWS  8192
#define NZ      32

typedef unsigned int u32;
typedef unsigned short u16;

// ----------------------- device scratch (no allocs) -----------------------
__device__ __align__(16) __nv_bfloat16 g_xs_h[M_ROWS * DIN_];
__device__ __align__(16) __nv_bfloat16 g_xs_l[M_ROWS * DIN_];
__device__ __align__(16) __nv_bfloat16 g_wq_h[QK_COLS * DIN_];
__device__ __align__(16) __nv_bfloat16 g_wq_l[QK_COLS * DIN_];
__device__ __align__(16) __nv_bfloat16 g_wk_h[QK_COLS * DIN_];
__device__ __align__(16) __nv_bfloat16 g_wk_l[QK_COLS * DIN_];
__device__ __align__(16) __nv_bfloat16 g_wv_h[V_COLS * DIN_];
__device__ __align__(16) __nv_bfloat16 g_wv_l[V_COLS * DIN_];
__device__ __align__(16) __nv_bfloat16 g_wo_h[V_COLS * V_COLS];
__device__ __align__(16) __nv_bfloat16 g_wo_l[V_COLS * V_COLS];
__device__ __align__(16) __nv_bfloat16 g_q_h[M_ROWS * QK_COLS];
__device__ __align__(16) __nv_bfloat16 g_q_l[M_ROWS * QK_COLS];
__device__ __align__(16) __nv_bfloat16 g_k_h[M_ROWS * QK_COLS];
__device__ __align__(16) __nv_bfloat16 g_k_l[M_ROWS * QK_COLS];
__device__ __align__(16) __nv_bfloat16 g_e_h[(size_t)NZ * C_LEN * C_LEN];
__device__ __align__(16) __nv_bfloat16 g_e_l[(size_t)NZ * C_LEN * C_LEN];
__device__ __align__(16) float         g_v [M_ROWS * V_COLS];
__device__ __align__(16) __nv_bfloat16 g_vt_h[M_ROWS * V_COLS];
__device__ __align__(16) __nv_bfloat16 g_vt_l[M_ROWS * V_COLS];
__device__ __align__(16) __nv_bfloat16 g_ao_h[M_ROWS * V_COLS];
__device__ __align__(16) __nv_bfloat16 g_ao_l[M_ROWS * V_COLS];
__device__ float g_sum[NZ * C_LEN];

// ----------------------- helpers -----------------------
__device__ __forceinline__ u32 smem_u32(const void* p) {
    return (u32)__cvta_generic_to_shared(p);
}
__device__ __forceinline__ void ldsm4(u32* r, u32 a) {
    asm volatile("ldmatrix.sync.aligned.m8n8.x4.shared.b16 {%0,%1,%2,%3}, [%4];\n"
                 : "=r"(r[0]), "=r"(r[1]), "=r"(r[2]), "=r"(r[3]) : "r"(a));
}
__device__ __forceinline__ void mma16816(float* d, const u32* a, u32 b0, u32 b1) {
    asm volatile(
        "mma.sync.aligned.m16n8k16.row.col.f32.bf16.bf16.f32 "
        "{%0,%1,%2,%3},{%4,%5,%6,%7},{%8,%9},{%0,%1,%2,%3};\n"
        : "+f"(d[0]), "+f"(d[1]), "+f"(d[2]), "+f"(d[3])
        : "r"(a[0]), "r"(a[1]), "r"(a[2]), "r"(a[3]), "r"(b0), "r"(b1));
}
__device__ __forceinline__ void pack_split(float a, float b, u32& hi, u32& lo) {
    __nv_bfloat16 ha = __float2bfloat16_rn(a), hb = __float2bfloat16_rn(b);
    __nv_bfloat16 la = __float2bfloat16_rn(a - __bfloat162float(ha));
    __nv_bfloat16 lb = __float2bfloat16_rn(b - __bfloat162float(hb));
    __nv_bfloat162 hp; hp.x = ha; hp.y = hb;
    __nv_bfloat162 lp; lp.x = la; lp.y = lb;
    hi = *(u32*)&hp; lo = *(u32*)&lp;
}
#define CP16(dst, src) asm volatile("cp.async.cg.shared.global [%0], [%1], 16;\n" :: "r"(dst), "l"(src))
#define CPCOMMIT()     asm volatile("cp.async.commit_group;\n")
#define CPWAIT(n)      asm volatile("cp.async.wait_group %0;\n" :: "n"(n))

// ----------------------- fp32 -> bf16 hi/lo split -----------------------
__global__ void __launch_bounds__(256) split_f32(
    const float* __restrict__ src, __nv_bfloat16* __restrict__ h,
    __nv_bfloat16* __restrict__ l, int n4)
{
    int i = blockIdx.x * 256 + threadIdx.x;
    if (i >= n4) return;
    float4 v = ((const float4*)src)[i];
    u32 h0, l0, h1, l1;
    pack_split(v.x, v.y, h0, l0);
    pack_split(v.z, v.w, h1, l1);
    uint2 hh; hh.x = h0; hh.y = h1;
    uint2 ll; ll.x = l0; ll.y = l1;
    ((uint2*)h)[i] = hh;
    ((uint2*)l)[i] = ll;
}

__global__ void zero_sum() { g_sum[blockIdx.x * 256 + threadIdx.x] = 0.f; }

// ---------------------------------------------------------------------------
// bf16 3-term NT GEMM, single-pass staging, cp.async double buffer.
// C = A@B^T; acc = AhBh + AlBh + AhBl.
// BM=128, BN=128, BK=16. 256 thr = 8 warps (4m x 2n), warp tile 32x64.
// MODE 0: fp32 out + bias. MODE 1: split bf16 out (+bias if non-null).
// MODE 2: E = exp((acc + mask[q])/8) -> split bf16 out + column-sum atomics.
// ---------------------------------------------------------------------------
#define STG (128 * 24)   // u16 per tile stage
template <int MODE>
__global__ void __launch_bounds__(256) gemm_bf3(
    const __nv_bfloat16* __restrict__ Ah, const __nv_bfloat16* __restrict__ Al,
    const __nv_bfloat16* __restrict__ Bh, const __nv_bfloat16* __restrict__ Bl,
    const float* __restrict__ bias, const float* __restrict__ mask,
    float* __restrict__ Cf,
    __nv_bfloat16* __restrict__ Ch, __nv_bfloat16* __restrict__ Cl,
    int K, int lda, int ldb, int ldc,
    size_t sA, size_t sB, size_t sC)
{
    __shared__ __align__(16) u16 sAh[2][STG];
    __shared__ __align__(16) u16 sAl[2][STG];
    __shared__ __align__(16) u16 sBh[2][STG];
    __shared__ __align__(16) u16 sBl[2][STG];

    const int tid = threadIdx.x;
    const int lane = tid & 31, wid = tid >> 5;
    const int wm = wid & 3, wn = wid >> 2;
    const int bm = blockIdx.y * 128, bn = blockIdx.x * 128;
    const int z = blockIdx.z;

    Ah += sA * z; Al += sA * z; Bh += sB * z; Bl += sB * z;
    if (Cf) Cf += sC * z;
    if (Ch) { Ch += sC * z; Cl += sC * z; }

    // staging: each thread copies one 16B piece per tile
    const int arow = tid >> 1, acol = (tid & 1) * 8;
    const size_t aoff = (size_t)(bm + arow) * lda + acol;
    const size_t boff = (size_t)(bn + arow) * ldb + acol;
    const u32 dAh = smem_u32(&sAh[0][arow * 24 + acol]);
    const u32 dAl = smem_u32(&sAl[0][arow * 24 + acol]);
    const u32 dBh = smem_u32(&sBh[0][arow * 24 + acol]);
    const u32 dBl = smem_u32(&sBl[0][arow * 24 + acol]);

    // ldmatrix base addresses (stage 0)
    const int grp = lane >> 3, l8 = lane & 7;
    const int amr = ((grp & 1) << 3) + l8, amc = (grp >> 1) << 3;
    const int bmr = ((grp >> 1) << 3) + l8, bmc = (grp & 1) << 3;
    u32 aH_ad[2], aL_ad[2], bH_ad[4], bL_ad[4];
#pragma unroll
    for (int mi = 0; mi < 2; mi++) {
        int r = wm * 32 + mi * 16 + amr;
        aH_ad[mi] = smem_u32(&sAh[0][r * 24 + amc]);
        aL_ad[mi] = smem_u32(&sAl[0][r * 24 + amc]);
    }
#pragma unroll
    for (int p = 0; p < 4; p++) {
        int r = wn * 64 + p * 16 + bmr;
        bH_ad[p] = smem_u32(&sBh[0][r * 24 + bmc]);
        bL_ad[p] = smem_u32(&sBl[0][r * 24 + bmc]);
    }

    float acc[2][8][4] = {};
    const int NC = K >> 4;

    auto stage = [&](int buf, int c) {
        const u32 so = buf * (STG * 2);
        const size_t k0 = (size_t)c << 4;
        CP16(dAh + so, Ah + aoff + k0);
        CP16(dAl + so, Al + aoff + k0);
        CP16(dBh + so, Bh + boff + k0);
        CP16(dBl + so, Bl + boff + k0);
    };

    stage(0, 0); CPCOMMIT();

    for (int c = 0; c < NC; ++c) {
        const int buf = c & 1;
        if (c + 1 < NC) { stage(buf ^ 1, c + 1); CPCOMMIT(); CPWAIT(1); }
        else CPWAIT(0);
        __syncthreads();

        const u32 so = buf * (STG * 2);
        u32 aH[2][4], aL[2][4], bH[4][4], bL[4][4];
#pragma unroll
        for (int mi = 0; mi < 2; mi++) {
            ldsm4(aH[mi], aH_ad[mi] + so);
            ldsm4(aL[mi], aL_ad[mi] + so);
        }
#pragma unroll
        for (int p = 0; p < 4; p++) {
            ldsm4(bH[p], bH_ad[p] + so);
            ldsm4(bL[p], bL_ad[p] + so);
        }
#pragma unroll
        for (int mi = 0; mi < 2; mi++)
#pragma unroll
            for (int ni = 0; ni < 8; ni++) {
                const int p = ni >> 1, q = (ni & 1) * 2;
                mma16816(acc[mi][ni], aH[mi], bH[p][q], bH[p][q + 1]);
                mma16816(acc[mi][ni], aL[mi], bH[p][q], bH[p][q + 1]);
                mma16816(acc[mi][ni], aH[mi], bL[p][q], bL[p][q + 1]);
            }
        __syncthreads();
    }

    // ----------------- epilogue -----------------
    const int lr = lane >> 2, lc2 = (lane & 3) * 2;
#pragma unroll
    for (int mi = 0; mi < 2; mi++) {
        const int m0 = bm + wm * 32 + mi * 16 + lr;
        float mk0 = 0.f, mk8 = 0.f;
        if (MODE == 2) {
            const float* mrow = mask + (size_t)(z >> 3) * C_LEN;
            mk0 = mrow[m0]; mk8 = mrow[m0 + 8];
        }
#pragma unroll
        for (int ni = 0; ni < 8; ni++) {
            const int n0 = bn + wn * 64 + ni * 8 + lc2;
            float c0 = acc[mi][ni][0], c1 = acc[mi][ni][1];
            float c2 = acc[mi][ni][2], c3 = acc[mi][ni][3];
            if (MODE == 0) {
                float b0 = bias[n0], b1 = bias[n0 + 1];
                float2 r0; r0.x = c0 + b0; r0.y = c1 + b1;
                float2 r1; r1.x = c2 + b0; r1.y = c3 + b1;
                *(float2*)(Cf + (size_t)m0 * ldc + n0) = r0;
                *(float2*)(Cf + (size_t)(m0 + 8) * ldc + n0) = r1;
            } else if (MODE == 1) {
                float b0 = 0.f, b1 = 0.f;
                if (bias) { b0 = bias[n0]; b1 = bias[n0 + 1]; }
                u32 h0, l0, h1, l1;
                pack_split(c0 + b0, c1 + b1, h0, l0);
                pack_split(c2 + b0, c3 + b1, h1, l1);
                *(u32*)(Ch + (size_t)m0 * ldc + n0) = h0;
                *(u32*)(Cl + (size_t)m0 * ldc + n0) = l0;
                *(u32*)(Ch + (size_t)(m0 + 8) * ldc + n0) = h1;
                *(u32*)(Cl + (size_t)(m0 + 8) * ldc + n0) = l1;
            } else { // MODE 2: exp + store + column-sum reduction
                float e0 = __expf((c0 + mk0) * 0.125f);
                float e1 = __expf((c1 + mk0) * 0.125f);
                float e2 = __expf((c2 + mk8) * 0.125f);
                float e3 = __expf((c3 + mk8) * 0.125f);
                u32 h0, l0, h1, l1;
                pack_split(e0, e1, h0, l0);
                pack_split(e2, e3, h1, l1);
                *(u32*)(Ch + (size_t)m0 * ldc + n0) = h0;
                *(u32*)(Cl + (size_t)m0 * ldc + n0) = l0;
                *(u32*)(Ch + (size_t)(m0 + 8) * ldc + n0) = h1;
                *(u32*)(Cl + (size_t)(m0 + 8) * ldc + n0) = l1;
                // sum over the 16 q-rows this warp's fragment covers
                float s0 = e0 + e2, s1 = e1 + e3;
                s0 += __shfl_xor_sync(0xffffffffu, s0, 4);
                s0 += __shfl_xor_sync(0xffffffffu, s0, 8);
                s0 += __shfl_xor_sync(0xffffffffu, s0, 16);
                s1 += __shfl_xor_sync(0xffffffffu, s1, 4);
                s1 += __shfl_xor_sync(0xffffffffu, s1, 8);
                s1 += __shfl_xor_sync(0xffffffffu, s1, 16);
                if (lane < 4) {
                    atomicAdd(&g_sum[z * C_LEN + n0], s0);
                    atomicAdd(&g_sum[z * C_LEN + n0 + 1], s1);
                }
            }
        }
    }
}

// ----------------------- V' transpose+scale: vt[z][d][k] = V[z][k][d]/sum[z][k] -----------------------
__global__ void __launch_bounds__(256) scale_v()
{
    __shared__ float t[32][33];
    const int z = blockIdx.z;
    const int k0 = blockIdx.x * 32, d0 = blockIdx.y * 32;
    const int tx = threadIdx.x & 31, ty = threadIdx.x >> 5;
    const size_t vbase = (size_t)z * (C_LEN * DV_);
#pragma unroll
    for (int i = 0; i < 4; i++)
        t[ty + i * 8][tx] = g_v[vbase + (size_t)(k0 + ty + i * 8) * DV_ + d0 + tx];
    __syncthreads();
    const float iv = 1.0f / g_sum[z * C_LEN + k0 + tx];
#pragma unroll
    for (int i = 0; i < 4; i++) {
        float val = t[tx][ty + i * 8] * iv;
        __nv_bfloat16 h = __float2bfloat16_rn(val);
        __nv_bfloat16 l = __float2bfloat16_rn(val - __bfloat162float(h));
        size_t o = vbase + (size_t)(d0 + ty + i * 8) * C_LEN + k0 + tx;
        g_vt_h[o] = h;
        g_vt_l[o] = l;
    }
}

// ---------------------------------------------------------------------------
extern "C" void kernel_launch(void* const* d_in, const int* in_sizes, int n_in,
                              void* d_out, int out_size)
{
    const float* x    = (const float*)d_in[0];
    const float* mask = (const float*)d_in[1];
    const float* Mq_w = (const float*)d_in[2];
    const float* Mq_b = (const float*)d_in[3];
    const float* Mk_w = (const float*)d_in[4];
    const float* Mk_b = (const float*)d_in[5];
    const float* Mv_w = (const float*)d_in[6];
    const float* Mv_b = (const float*)d_in[7];
    const float* Wo_w = (const float*)d_in[8];
    const float* Wo_b = (const float*)d_in[9];
    float* out = (float*)d_out;

    __nv_bfloat16 *xs_h, *xs_l, *wq_h, *wq_l, *wk_h, *wk_l, *wv_h, *wv_l;
    __nv_bfloat16 *wo_h, *wo_l, *q_h, *q_l, *k_h, *k_l, *e_h, *e_l;
    __nv_bfloat16 *vt_h, *vt_l, *ao_h, *ao_l;
    float *v;
    cudaGetSymbolAddress((void**)&xs_h, g_xs_h); cudaGetSymbolAddress((void**)&xs_l, g_xs_l);
    cudaGetSymbolAddress((void**)&wq_h, g_wq_h); cudaGetSymbolAddress((void**)&wq_l, g_wq_l);
    cudaGetSymbolAddress((void**)&wk_h, g_wk_h); cudaGetSymbolAddress((void**)&wk_l, g_wk_l);
    cudaGetSymbolAddress((void**)&wv_h, g_wv_h); cudaGetSymbolAddress((void**)&wv_l, g_wv_l);
    cudaGetSymbolAddress((void**)&wo_h, g_wo_h); cudaGetSymbolAddress((void**)&wo_l, g_wo_l);
    cudaGetSymbolAddress((void**)&q_h,  g_q_h);  cudaGetSymbolAddress((void**)&q_l,  g_q_l);
    cudaGetSymbolAddress((void**)&k_h,  g_k_h);  cudaGetSymbolAddress((void**)&k_l,  g_k_l);
    cudaGetSymbolAddress((void**)&e_h,  g_e_h);  cudaGetSymbolAddress((void**)&e_l,  g_e_l);
    cudaGetSymbolAddress((void**)&vt_h, g_vt_h); cudaGetSymbolAddress((void**)&vt_l, g_vt_l);
    cudaGetSymbolAddress((void**)&ao_h, g_ao_h); cudaGetSymbolAddress((void**)&ao_l, g_ao_l);
    cudaGetSymbolAddress((void**)&v,    g_v);

    dim3 blk(256);

    split_f32<<<(M_ROWS * DIN_ / 4 + 255) / 256, blk>>>(x, xs_h, xs_l, M_ROWS * DIN_ / 4);
    split_f32<<<(QK_COLS * DIN_ / 4 + 255) / 256, blk>>>(Mq_w, wq_h, wq_l, QK_COLS * DIN_ / 4);
    split_f32<<<(QK_COLS * DIN_ / 4 + 255) / 256, blk>>>(Mk_w, wk_h, wk_l, QK_COLS * DIN_ / 4);
    split_f32<<<(V_COLS * DIN_ / 4 + 255) / 256, blk>>>(Mv_w, wv_h, wv_l, V_COLS * DIN_ / 4);
    split_f32<<<(V_COLS * V_COLS / 4 + 255) / 256, blk>>>(Wo_w, wo_h, wo_l, V_COLS * V_COLS / 4);
    zero_sum<<<NZ * C_LEN / 256, blk>>>();

    // Q, K projections -> split bf16
    gemm_bf3<1><<<dim3(QK_COLS / 128, M_ROWS / 128, 1), blk>>>(
        xs_h, xs_l, wq_h, wq_l, Mq_b, nullptr, nullptr, q_h, q_l,
        DIN_, DIN_, DIN_, QK_COLS, 0, 0, 0);
    gemm_bf3<1><<<dim3(QK_COLS / 128, M_ROWS / 128, 1), blk>>>(
        xs_h, xs_l, wk_h, wk_l, Mk_b, nullptr, nullptr, k_h, k_l,
        DIN_, DIN_, DIN_, QK_COLS, 0, 0, 0);
    // V projection -> fp32
    gemm_bf3<0><<<dim3(V_COLS / 128, M_ROWS / 128, 1), blk>>>(
        xs_h, xs_l, wv_h, wv_l, Mv_b, nullptr, v, nullptr, nullptr,
        DIN_, DIN_, DIN_, V_COLS, 0, 0, 0);

    // scores -> E = exp((QK^T+mask)/8) + column sums, batched over z
    gemm_bf3<2><<<dim3(C_LEN / 128, C_LEN / 128, NZ), blk>>>(
        q_h, q_l, k_h, k_l, nullptr, mask, nullptr, e_h, e_l,
        DK_, DK_, DK_, C_LEN,
        (size_t)C_LEN * DK_, (size_t)C_LEN * DK_, (size_t)C_LEN * C_LEN);

    // V' = V/sum, transposed to [z][d][k], split bf16
    scale_v<<<dim3(C_LEN / 32, DV_ / 32, NZ), blk>>>();

    // AO = E @ V'^T, split bf16 out
    gemm_bf3<1><<<dim3(DV_ / 128, C_LEN / 128, NZ), blk>>>(
        e_h, e_l, vt_h, vt_l, nullptr, nullptr, nullptr, ao_h, ao_l,
        C_LEN, C_LEN, C_LEN, DV_,
        (size_t)C_LEN * C_LEN, (size_t)C_LEN * DV_, (size_t)C_LEN * DV_);

    // out projection -> d_out fp32
    gemm_bf3<0><<<dim3(V_COLS / 128, M_ROWS / 128, 1), blk>>>(
        ao_h, ao_l, wo_h, wo_l, Wo_b, nullptr, out, nullptr, nullptr,
        V_COLS, V_COLS, V_COLS, V_COLS, 0, 0, 0);
}

// round 7
// speedup vs baseline: 3.2863x; 1.3490x over previous
#include <cuda_runtime.h>
#include <cuda_fp16.h>
#include <cstdint>

#define B_SZ   4
#define C_LEN  2048
#define H_N    8
#define DK_    64
#define DV_    128
#define DIN_   1024
#define QK_COLS 512
#define V_COLS  1024
#define M_ROWS  8192
#define NZ      32

typedef unsigned int u32;
typedef unsigned short u16;

// ----------------------- device scratch (no allocs) -----------------------
__device__ __align__(16) __half g_xs_h[M_ROWS * DIN_];
__device__ __align__(16) __half g_xs_l[M_ROWS * DIN_];
__device__ __align__(16) __half g_wq_h[QK_COLS * DIN_];
__device__ __align__(16) __half g_wk_h[QK_COLS * DIN_];
__device__ __align__(16) __half g_wv_h[V_COLS * DIN_];
__device__ __align__(16) __half g_wo_h[V_COLS * V_COLS];
__device__ __align__(16) __half g_q_h[M_ROWS * QK_COLS];
__device__ __align__(16) __half g_q_l[M_ROWS * QK_COLS];
__device__ __align__(16) __half g_k_h[M_ROWS * QK_COLS];
__device__ __align__(16) __half g_e_h[(size_t)NZ * C_LEN * C_LEN];  // 256MB
__device__ __align__(16) __half g_e_l[(size_t)NZ * C_LEN * C_LEN];  // 256MB
__device__ __align__(16) float  g_v [M_ROWS * V_COLS];
__device__ __align__(16) __half g_vt_h[M_ROWS * V_COLS];
__device__ __align__(16) __half g_ao_h[M_ROWS * V_COLS];
__device__ __align__(16) __half g_ao_l[M_ROWS * V_COLS];
__device__ float g_sum[NZ * C_LEN];

// ----------------------- helpers -----------------------
__device__ __forceinline__ u32 smem_u32(const void* p) {
    return (u32)__cvta_generic_to_shared(p);
}
__device__ __forceinline__ void ldsm4(u32* r, u32 a) {
    asm volatile("ldmatrix.sync.aligned.m8n8.x4.shared.b16 {%0,%1,%2,%3}, [%4];\n"
                 : "=r"(r[0]), "=r"(r[1]), "=r"(r[2]), "=r"(r[3]) : "r"(a));
}
__device__ __forceinline__ void mma16816(float* d, const u32* a, u32 b0, u32 b1) {
    asm volatile(
        "mma.sync.aligned.m16n8k16.row.col.f32.f16.f16.f32 "
        "{%0,%1,%2,%3},{%4,%5,%6,%7},{%8,%9},{%0,%1,%2,%3};\n"
        : "+f"(d[0]), "+f"(d[1]), "+f"(d[2]), "+f"(d[3])
        : "r"(a[0]), "r"(a[1]), "r"(a[2]), "r"(a[3]), "r"(b0), "r"(b1));
}
// split (a,b) -> packed fp16x2 hi and lo
__device__ __forceinline__ void pack_split(float a, float b, u32& hi, u32& lo) {
    __half ha = __float2half_rn(a), hb = __float2half_rn(b);
    __half la = __float2half_rn(a - __half2float(ha));
    __half lb = __float2half_rn(b - __half2float(hb));
    __half2 hp; hp.x = ha; hp.y = hb;
    __half2 lp; lp.x = la; lp.y = lb;
    hi = *(u32*)&hp; lo = *(u32*)&lp;
}
#define CP16(dst, src) asm volatile("cp.async.cg.shared.global [%0], [%1], 16;\n" :: "r"(dst), "l"(src))
#define CPCOMMIT()     asm volatile("cp.async.commit_group;\n")
#define CPWAIT(n)      asm volatile("cp.async.wait_group %0;\n" :: "n"(n))

// ----------------------- fp32 -> fp16 hi/lo split (lo optional) -----------------------
__global__ void __launch_bounds__(256) split_f32(
    const float* __restrict__ src, __half* __restrict__ h,
    __half* __restrict__ l, int n4)
{
    int i = blockIdx.x * 256 + threadIdx.x;
    if (i >= n4) return;
    float4 v = ((const float4*)src)[i];
    u32 h0, l0, h1, l1;
    pack_split(v.x, v.y, h0, l0);
    pack_split(v.z, v.w, h1, l1);
    uint2 hh; hh.x = h0; hh.y = h1;
    ((uint2*)h)[i] = hh;
    if (l) {
        uint2 ll; ll.x = l0; ll.y = l1;
        ((uint2*)l)[i] = ll;
    }
}

__global__ void zero_sum() { g_sum[blockIdx.x * 256 + threadIdx.x] = 0.f; }

// ---------------------------------------------------------------------------
// fp16 2-term NT GEMM: C = A@B^T; acc = AhBh + AlBh  (A split hi/lo, B hi only)
// BM=128, BN=128, BK=16. 256 thr = 8 warps (4m x 2n), warp tile 32x64.
// cp.async double buffer. MODE 0: fp32 out = acc*cscale + bias.
// MODE 1: split fp16 out = acc*cscale (+bias); lo written iff Cl != null.
// MODE 2: E = exp((acc + mask[q])/8) -> split fp16 out + column-sum atomics.
// ---------------------------------------------------------------------------
#define STG (128 * 24)   // u16 per tile stage
template <int MODE>
__global__ void __launch_bounds__(256) gemm_h2(
    const __half* __restrict__ Ah, const __half* __restrict__ Al,
    const __half* __restrict__ Bh,
    const float* __restrict__ bias, const float* __restrict__ mask, float cscale,
    float* __restrict__ Cf, __half* __restrict__ Ch, __half* __restrict__ Cl,
    int K, int lda, int ldb, int ldc,
    size_t sA, size_t sB, size_t sC)
{
    __shared__ __align__(16) u16 sAh[2][STG];
    __shared__ __align__(16) u16 sAl[2][STG];
    __shared__ __align__(16) u16 sBh[2][STG];

    const int tid = threadIdx.x;
    const int lane = tid & 31, wid = tid >> 5;
    const int wm = wid & 3, wn = wid >> 2;
    const int bm = blockIdx.y * 128, bn = blockIdx.x * 128;
    const int z = blockIdx.z;

    Ah += sA * z; Al += sA * z; Bh += sB * z;
    if (Cf) Cf += sC * z;
    if (Ch) Ch += sC * z;
    if (Cl) Cl += sC * z;

    // staging: each thread copies one 16B piece per tile
    const int arow = tid >> 1, acol = (tid & 1) * 8;
    const size_t aoff = (size_t)(bm + arow) * lda + acol;
    const size_t boff = (size_t)(bn + arow) * ldb + acol;
    const u32 dAh = smem_u32(&sAh[0][arow * 24 + acol]);
    const u32 dAl = smem_u32(&sAl[0][arow * 24 + acol]);
    const u32 dBh = smem_u32(&sBh[0][arow * 24 + acol]);

    // ldmatrix base addresses (stage 0)
    const int grp = lane >> 3, l8 = lane & 7;
    const int amr = ((grp & 1) << 3) + l8, amc = (grp >> 1) << 3;
    const int bmr = ((grp >> 1) << 3) + l8, bmc = (grp & 1) << 3;
    u32 aH_ad[2], aL_ad[2], bH_ad[4];
#pragma unroll
    for (int mi = 0; mi < 2; mi++) {
        int r = wm * 32 + mi * 16 + amr;
        aH_ad[mi] = smem_u32(&sAh[0][r * 24 + amc]);
        aL_ad[mi] = smem_u32(&sAl[0][r * 24 + amc]);
    }
#pragma unroll
    for (int p = 0; p < 4; p++) {
        int r = wn * 64 + p * 16 + bmr;
        bH_ad[p] = smem_u32(&sBh[0][r * 24 + bmc]);
    }

    float acc[2][8][4] = {};
    const int NC = K >> 4;

    auto stage = [&](int buf, int c) {
        const u32 so = buf * (STG * 2);
        const size_t k0 = (size_t)c << 4;
        CP16(dAh + so, Ah + aoff + k0);
        CP16(dAl + so, Al + aoff + k0);
        CP16(dBh + so, Bh + boff + k0);
    };

    stage(0, 0); CPCOMMIT();

    for (int c = 0; c < NC; ++c) {
        const int buf = c & 1;
        if (c + 1 < NC) { stage(buf ^ 1, c + 1); CPCOMMIT(); CPWAIT(1); }
        else CPWAIT(0);
        __syncthreads();

        const u32 so = buf * (STG * 2);
        u32 aH[2][4], aL[2][4], bH[4][4];
#pragma unroll
        for (int mi = 0; mi < 2; mi++) {
            ldsm4(aH[mi], aH_ad[mi] + so);
            ldsm4(aL[mi], aL_ad[mi] + so);
        }
#pragma unroll
        for (int p = 0; p < 4; p++)
            ldsm4(bH[p], bH_ad[p] + so);
#pragma unroll
        for (int mi = 0; mi < 2; mi++)
#pragma unroll
            for (int ni = 0; ni < 8; ni++) {
                const int p = ni >> 1, q = (ni & 1) * 2;
                mma16816(acc[mi][ni], aH[mi], bH[p][q], bH[p][q + 1]);
                mma16816(acc[mi][ni], aL[mi], bH[p][q], bH[p][q + 1]);
            }
        __syncthreads();
    }

    // ----------------- epilogue -----------------
    const int lr = lane >> 2, lc2 = (lane & 3) * 2;
#pragma unroll
    for (int mi = 0; mi < 2; mi++) {
        const int m0 = bm + wm * 32 + mi * 16 + lr;
        float mk0 = 0.f, mk8 = 0.f;
        if (MODE == 2) {
            const float* mrow = mask + (size_t)(z >> 3) * C_LEN;
            mk0 = mrow[m0]; mk8 = mrow[m0 + 8];
        }
#pragma unroll
        for (int ni = 0; ni < 8; ni++) {
            const int n0 = bn + wn * 64 + ni * 8 + lc2;
            float c0 = acc[mi][ni][0], c1 = acc[mi][ni][1];
            float c2 = acc[mi][ni][2], c3 = acc[mi][ni][3];
            if (MODE == 0) {
                float b0 = bias[n0], b1 = bias[n0 + 1];
                float2 r0; r0.x = c0 * cscale + b0; r0.y = c1 * cscale + b1;
                float2 r1; r1.x = c2 * cscale + b0; r1.y = c3 * cscale + b1;
                *(float2*)(Cf + (size_t)m0 * ldc + n0) = r0;
                *(float2*)(Cf + (size_t)(m0 + 8) * ldc + n0) = r1;
            } else if (MODE == 1) {
                float b0 = 0.f, b1 = 0.f;
                if (bias) { b0 = bias[n0]; b1 = bias[n0 + 1]; }
                u32 h0, l0, h1, l1;
                pack_split(c0 * cscale + b0, c1 * cscale + b1, h0, l0);
                pack_split(c2 * cscale + b0, c3 * cscale + b1, h1, l1);
                *(u32*)(Ch + (size_t)m0 * ldc + n0) = h0;
                *(u32*)(Ch + (size_t)(m0 + 8) * ldc + n0) = h1;
                if (Cl) {
                    *(u32*)(Cl + (size_t)m0 * ldc + n0) = l0;
                    *(u32*)(Cl + (size_t)(m0 + 8) * ldc + n0) = l1;
                }
            } else { // MODE 2: exp + store + column-sum reduction
                float e0 = __expf((c0 + mk0) * 0.125f);
                float e1 = __expf((c1 + mk0) * 0.125f);
                float e2 = __expf((c2 + mk8) * 0.125f);
                float e3 = __expf((c3 + mk8) * 0.125f);
                u32 h0, l0, h1, l1;
                pack_split(e0, e1, h0, l0);
                pack_split(e2, e3, h1, l1);
                *(u32*)(Ch + (size_t)m0 * ldc + n0) = h0;
                *(u32*)(Cl + (size_t)m0 * ldc + n0) = l0;
                *(u32*)(Ch + (size_t)(m0 + 8) * ldc + n0) = h1;
                *(u32*)(Cl + (size_t)(m0 + 8) * ldc + n0) = l1;
                // sum over the 16 q-rows this warp's fragment covers
                float s0 = e0 + e2, s1 = e1 + e3;
                s0 += __shfl_xor_sync(0xffffffffu, s0, 4);
                s0 += __shfl_xor_sync(0xffffffffu, s0, 8);
                s0 += __shfl_xor_sync(0xffffffffu, s0, 16);
                s1 += __shfl_xor_sync(0xffffffffu, s1, 4);
                s1 += __shfl_xor_sync(0xffffffffu, s1, 8);
                s1 += __shfl_xor_sync(0xffffffffu, s1, 16);
                if (lane < 4) {
                    atomicAdd(&g_sum[z * C_LEN + n0], s0);
                    atomicAdd(&g_sum[z * C_LEN + n0 + 1], s1);
                }
            }
        }
    }
}

// ------- V'' transpose+scale: vt[z][d][k] = V[z][k][d] * 2048 / sum[z][k] -------
// (x2048 keeps V'' O(1) in fp16; the exact 1/2048 is folded into the AV epilogue)
__global__ void __launch_bounds__(256) scale_v()
{
    __shared__ float t[32][33];
    const int z = blockIdx.z;
    const int k0 = blockIdx.x * 32, d0 = blockIdx.y * 32;
    const int tx = threadIdx.x & 31, ty = threadIdx.x >> 5;
    const size_t vbase = (size_t)z * (C_LEN * DV_);
#pragma unroll
    for (int i = 0; i < 4; i++)
        t[ty + i * 8][tx] = g_v[vbase + (size_t)(k0 + ty + i * 8) * DV_ + d0 + tx];
    __syncthreads();
    const float iv = 2048.0f / g_sum[z * C_LEN + k0 + tx];
#pragma unroll
    for (int i = 0; i < 4; i++) {
        float val = t[tx][ty + i * 8] * iv;
        size_t o = vbase + (size_t)(d0 + ty + i * 8) * C_LEN + k0 + tx;
        g_vt_h[o] = __float2half_rn(val);
    }
}

// ---------------------------------------------------------------------------
extern "C" void kernel_launch(void* const* d_in, const int* in_sizes, int n_in,
                              void* d_out, int out_size)
{
    const float* x    = (const float*)d_in[0];
    const float* mask = (const float*)d_in[1];
    const float* Mq_w = (const float*)d_in[2];
    const float* Mq_b = (const float*)d_in[3];
    const float* Mk_w = (const float*)d_in[4];
    const float* Mk_b = (const float*)d_in[5];
    const float* Mv_w = (const float*)d_in[6];
    const float* Mv_b = (const float*)d_in[7];
    const float* Wo_w = (const float*)d_in[8];
    const float* Wo_b = (const float*)d_in[9];
    float* out = (float*)d_out;

    __half *xs_h, *xs_l, *wq_h, *wk_h, *wv_h, *wo_h;
    __half *q_h, *q_l, *k_h, *e_h, *e_l, *vt_h, *ao_h, *ao_l;
    float *v;
    cudaGetSymbolAddress((void**)&xs_h, g_xs_h); cudaGetSymbolAddress((void**)&xs_l, g_xs_l);
    cudaGetSymbolAddress((void**)&wq_h, g_wq_h);
    cudaGetSymbolAddress((void**)&wk_h, g_wk_h);
    cudaGetSymbolAddress((void**)&wv_h, g_wv_h);
    cudaGetSymbolAddress((void**)&wo_h, g_wo_h);
    cudaGetSymbolAddress((void**)&q_h,  g_q_h);  cudaGetSymbolAddress((void**)&q_l,  g_q_l);
    cudaGetSymbolAddress((void**)&k_h,  g_k_h);
    cudaGetSymbolAddress((void**)&e_h,  g_e_h);  cudaGetSymbolAddress((void**)&e_l,  g_e_l);
    cudaGetSymbolAddress((void**)&vt_h, g_vt_h);
    cudaGetSymbolAddress((void**)&ao_h, g_ao_h); cudaGetSymbolAddress((void**)&ao_l, g_ao_l);
    cudaGetSymbolAddress((void**)&v,    g_v);

    dim3 blk(256);

    // splits: x -> hi+lo; weights -> hi only
    split_f32<<<(M_ROWS * DIN_ / 4 + 255) / 256, blk>>>(x, xs_h, xs_l, M_ROWS * DIN_ / 4);
    split_f32<<<(QK_COLS * DIN_ / 4 + 255) / 256, blk>>>(Mq_w, wq_h, nullptr, QK_COLS * DIN_ / 4);
    split_f32<<<(QK_COLS * DIN_ / 4 + 255) / 256, blk>>>(Mk_w, wk_h, nullptr, QK_COLS * DIN_ / 4);
    split_f32<<<(V_COLS * DIN_ / 4 + 255) / 256, blk>>>(Mv_w, wv_h, nullptr, V_COLS * DIN_ / 4);
    split_f32<<<(V_COLS * V_COLS / 4 + 255) / 256, blk>>>(Wo_w, wo_h, nullptr, V_COLS * V_COLS / 4);
    zero_sum<<<NZ * C_LEN / 256, blk>>>();

    // Q projection -> split fp16 (Q is the split operand of the scores GEMM)
    gemm_h2<1><<<dim3(QK_COLS / 128, M_ROWS / 128, 1), blk>>>(
        xs_h, xs_l, wq_h, Mq_b, nullptr, 1.0f, nullptr, q_h, q_l,
        DIN_, DIN_, DIN_, QK_COLS, 0, 0, 0);
    // K projection -> fp16 hi only
    gemm_h2<1><<<dim3(QK_COLS / 128, M_ROWS / 128, 1), blk>>>(
        xs_h, xs_l, wk_h, Mk_b, nullptr, 1.0f, nullptr, k_h, nullptr,
        DIN_, DIN_, DIN_, QK_COLS, 0, 0, 0);
    // V projection -> fp32
    gemm_h2<0><<<dim3(V_COLS / 128, M_ROWS / 128, 1), blk>>>(
        xs_h, xs_l, wv_h, Mv_b, nullptr, 1.0f, v, nullptr, nullptr,
        DIN_, DIN_, DIN_, V_COLS, 0, 0, 0);

    // scores -> E = exp((QK^T+mask)/8) + column sums, batched over z
    gemm_h2<2><<<dim3(C_LEN / 128, C_LEN / 128, NZ), blk>>>(
        q_h, q_l, k_h, nullptr, mask, 1.0f, nullptr, e_h, e_l,
        DK_, DK_, DK_, C_LEN,
        (size_t)C_LEN * DK_, (size_t)C_LEN * DK_, (size_t)C_LEN * C_LEN);

    // V'' = V*2048/sum, transposed to [z][d][k], fp16 hi only
    scale_v<<<dim3(C_LEN / 32, DV_ / 32, NZ), blk>>>();

    // AO = (E @ V''^T) / 2048, split fp16 out
    gemm_h2<1><<<dim3(DV_ / 128, C_LEN / 128, NZ), blk>>>(
        e_h, e_l, vt_h, nullptr, nullptr, 1.0f / 2048.0f, nullptr, ao_h, ao_l,
        C_LEN, C_LEN, C_LEN, DV_,
        (size_t)C_LEN * C_LEN, (size_t)C_LEN * DV_, (size_t)C_LEN * DV_);

    // out projection -> d_out fp32
    gemm_h2<0><<<dim3(V_COLS / 128, M_ROWS / 128, 1), blk>>>(
        ao_h, ao_l, wo_h, Wo_b, nullptr, 1.0f, out, nullptr, nullptr,
        V_COLS, V_COLS, V_COLS, V_COLS, 0, 0, 0);
}

// round 8
// speedup vs baseline: 3.9968x; 1.2162x over previous
#include <cuda_runtime.h>
#include <cuda_fp16.h>
#include <cstdint>

#define B_SZ   4
#define C_LEN  2048
#define H_N    8
#define DK_    64
#define DV_    128
#define DIN_   1024
#define QK_COLS 512
#define V_COLS  1024
#define M_ROWS  8192
#define NZ      32

typedef unsigned int u32;
typedef unsigned short u16;

// ----------------------- device scratch (no allocs) -----------------------
__device__ __align__(16) __half g_xs_h[M_ROWS * DIN_];
__device__ __align__(16) __half g_xs_l[M_ROWS * DIN_];
__device__ __align__(16) __half g_wq_h[QK_COLS * DIN_];
__device__ __align__(16) __half g_wk_h[QK_COLS * DIN_];
__device__ __align__(16) __half g_wv_h[V_COLS * DIN_];
__device__ __align__(16) __half g_wo_h[V_COLS * V_COLS];
__device__ __align__(16) __half g_q_h[M_ROWS * QK_COLS];
__device__ __align__(16) __half g_q_l[M_ROWS * QK_COLS];
__device__ __align__(16) __half g_k_h[M_ROWS * QK_COLS];
__device__ __align__(16) __half g_e_h[(size_t)NZ * C_LEN * C_LEN];  // 256MB
__device__ __align__(16) float  g_v [M_ROWS * V_COLS];
__device__ __align__(16) __half g_vt_h[M_ROWS * V_COLS];
__device__ __align__(16) __half g_ao_h[M_ROWS * V_COLS];
__device__ __align__(16) __half g_ao_l[M_ROWS * V_COLS];
__device__ float g_sum[NZ * C_LEN];

// ----------------------- helpers -----------------------
__device__ __forceinline__ u32 smem_u32(const void* p) {
    return (u32)__cvta_generic_to_shared(p);
}
__device__ __forceinline__ void ldsm4(u32* r, u32 a) {
    asm volatile("ldmatrix.sync.aligned.m8n8.x4.shared.b16 {%0,%1,%2,%3}, [%4];\n"
                 : "=r"(r[0]), "=r"(r[1]), "=r"(r[2]), "=r"(r[3]) : "r"(a));
}
__device__ __forceinline__ void mma16816(float* d, const u32* a, u32 b0, u32 b1) {
    asm volatile(
        "mma.sync.aligned.m16n8k16.row.col.f32.f16.f16.f32 "
        "{%0,%1,%2,%3},{%4,%5,%6,%7},{%8,%9},{%0,%1,%2,%3};\n"
        : "+f"(d[0]), "+f"(d[1]), "+f"(d[2]), "+f"(d[3])
        : "r"(a[0]), "r"(a[1]), "r"(a[2]), "r"(a[3]), "r"(b0), "r"(b1));
}
// split (a,b) -> packed fp16x2 hi and lo
__device__ __forceinline__ void pack_split(float a, float b, u32& hi, u32& lo) {
    __half ha = __float2half_rn(a), hb = __float2half_rn(b);
    __half la = __float2half_rn(a - __half2float(ha));
    __half lb = __float2half_rn(b - __half2float(hb));
    __half2 hp; hp.x = ha; hp.y = hb;
    __half2 lp; lp.x = la; lp.y = lb;
    hi = *(u32*)&hp; lo = *(u32*)&lp;
}
#define CP16(dst, src) asm volatile("cp.async.cg.shared.global [%0], [%1], 16;\n" :: "r"(dst), "l"(src))
#define CPCOMMIT()     asm volatile("cp.async.commit_group;\n")
#define CPWAIT(n)      asm volatile("cp.async.wait_group %0;\n" :: "n"(n))

// ----------------------- fp32 -> fp16 hi/lo split (lo optional) -----------------------
__global__ void __launch_bounds__(256) split_f32(
    const float* __restrict__ src, __half* __restrict__ h,
    __half* __restrict__ l, int n4)
{
    int i = blockIdx.x * 256 + threadIdx.x;
    if (i >= n4) return;
    float4 v = ((const float4*)src)[i];
    u32 h0, l0, h1, l1;
    pack_split(v.x, v.y, h0, l0);
    pack_split(v.z, v.w, h1, l1);
    uint2 hh; hh.x = h0; hh.y = h1;
    ((uint2*)h)[i] = hh;
    if (l) {
        uint2 ll; ll.x = l0; ll.y = l1;
        ((uint2*)l)[i] = ll;
    }
}

__global__ void zero_sum() { g_sum[blockIdx.x * 256 + threadIdx.x] = 0.f; }

// ---------------------------------------------------------------------------
// fp16 NT GEMM: C = A@B^T; acc = AhBh (+ AlBh if TERMS==2).
// BM=128, BN=128, BK=16. 256 thr = 8 warps (4m x 2n), warp tile 32x64.
// cp.async double buffer. MODE 0: fp32 out = acc*cscale + bias.
// MODE 1: split fp16 out = acc*cscale (+bias); lo written iff Cl != null.
// MODE 2: E = exp((acc + mask[q])/8) -> fp16 hi out + column sums of the
//         ROUNDED values (exact renormalization downstream).
// ---------------------------------------------------------------------------
#define STG (128 * 24)   // u16 per tile stage
template <int MODE, int TERMS>
__global__ void __launch_bounds__(256) gemm_h2(
    const __half* __restrict__ Ah, const __half* __restrict__ Al,
    const __half* __restrict__ Bh,
    const float* __restrict__ bias, const float* __restrict__ mask, float cscale,
    float* __restrict__ Cf, __half* __restrict__ Ch, __half* __restrict__ Cl,
    int K, int lda, int ldb, int ldc,
    size_t sA, size_t sB, size_t sC)
{
    __shared__ __align__(16) u16 sAh[2][STG];
    __shared__ __align__(16) u16 sAl[TERMS == 2 ? 2 : 1][STG];
    __shared__ __align__(16) u16 sBh[2][STG];

    const int tid = threadIdx.x;
    const int lane = tid & 31, wid = tid >> 5;
    const int wm = wid & 3, wn = wid >> 2;
    const int bm = blockIdx.y * 128, bn = blockIdx.x * 128;
    const int z = blockIdx.z;

    Ah += sA * z; Bh += sB * z;
    if (TERMS == 2) Al += sA * z;
    if (Cf) Cf += sC * z;
    if (Ch) Ch += sC * z;
    if (Cl) Cl += sC * z;

    // staging: each thread copies one 16B piece per tile
    const int arow = tid >> 1, acol = (tid & 1) * 8;
    const size_t aoff = (size_t)(bm + arow) * lda + acol;
    const size_t boff = (size_t)(bn + arow) * ldb + acol;
    const u32 dAh = smem_u32(&sAh[0][arow * 24 + acol]);
    const u32 dAl = smem_u32(&sAl[0][arow * 24 + acol]);
    const u32 dBh = smem_u32(&sBh[0][arow * 24 + acol]);

    // ldmatrix base addresses (stage 0)
    const int grp = lane >> 3, l8 = lane & 7;
    const int amr = ((grp & 1) << 3) + l8, amc = (grp >> 1) << 3;
    const int bmr = ((grp >> 1) << 3) + l8, bmc = (grp & 1) << 3;
    u32 aH_ad[2], aL_ad[2], bH_ad[4];
#pragma unroll
    for (int mi = 0; mi < 2; mi++) {
        int r = wm * 32 + mi * 16 + amr;
        aH_ad[mi] = smem_u32(&sAh[0][r * 24 + amc]);
        aL_ad[mi] = smem_u32(&sAl[0][r * 24 + amc]);
    }
#pragma unroll
    for (int p = 0; p < 4; p++) {
        int r = wn * 64 + p * 16 + bmr;
        bH_ad[p] = smem_u32(&sBh[0][r * 24 + bmc]);
    }

    float acc[2][8][4] = {};
    const int NC = K >> 4;

    auto stage = [&](int buf, int c) {
        const u32 so = buf * (STG * 2);
        const size_t k0 = (size_t)c << 4;
        CP16(dAh + so, Ah + aoff + k0);
        if (TERMS == 2) CP16(dAl + so, Al + aoff + k0);
        CP16(dBh + so, Bh + boff + k0);
    };

    stage(0, 0); CPCOMMIT();

    for (int c = 0; c < NC; ++c) {
        const int buf = c & 1;
        if (c + 1 < NC) { stage(buf ^ 1, c + 1); CPCOMMIT(); CPWAIT(1); }
        else CPWAIT(0);
        __syncthreads();

        const u32 so = buf * (STG * 2);
        u32 aH[2][4], aL[2][4], bH[4][4];
#pragma unroll
        for (int mi = 0; mi < 2; mi++) {
            ldsm4(aH[mi], aH_ad[mi] + so);
            if (TERMS == 2) ldsm4(aL[mi], aL_ad[mi] + so);
        }
#pragma unroll
        for (int p = 0; p < 4; p++)
            ldsm4(bH[p], bH_ad[p] + so);
#pragma unroll
        for (int mi = 0; mi < 2; mi++)
#pragma unroll
            for (int ni = 0; ni < 8; ni++) {
                const int p = ni >> 1, q = (ni & 1) * 2;
                mma16816(acc[mi][ni], aH[mi], bH[p][q], bH[p][q + 1]);
                if (TERMS == 2)
                    mma16816(acc[mi][ni], aL[mi], bH[p][q], bH[p][q + 1]);
            }
        __syncthreads();
    }

    // ----------------- epilogue -----------------
    const int lr = lane >> 2, lc2 = (lane & 3) * 2;
#pragma unroll
    for (int mi = 0; mi < 2; mi++) {
        const int m0 = bm + wm * 32 + mi * 16 + lr;
        float mk0 = 0.f, mk8 = 0.f;
        if (MODE == 2) {
            const float* mrow = mask + (size_t)(z >> 3) * C_LEN;
            mk0 = mrow[m0]; mk8 = mrow[m0 + 8];
        }
#pragma unroll
        for (int ni = 0; ni < 8; ni++) {
            const int n0 = bn + wn * 64 + ni * 8 + lc2;
            float c0 = acc[mi][ni][0], c1 = acc[mi][ni][1];
            float c2 = acc[mi][ni][2], c3 = acc[mi][ni][3];
            if (MODE == 0) {
                float b0 = bias[n0], b1 = bias[n0 + 1];
                float2 r0; r0.x = c0 * cscale + b0; r0.y = c1 * cscale + b1;
                float2 r1; r1.x = c2 * cscale + b0; r1.y = c3 * cscale + b1;
                *(float2*)(Cf + (size_t)m0 * ldc + n0) = r0;
                *(float2*)(Cf + (size_t)(m0 + 8) * ldc + n0) = r1;
            } else if (MODE == 1) {
                float b0 = 0.f, b1 = 0.f;
                if (bias) { b0 = bias[n0]; b1 = bias[n0 + 1]; }
                u32 h0, l0, h1, l1;
                pack_split(c0 * cscale + b0, c1 * cscale + b1, h0, l0);
                pack_split(c2 * cscale + b0, c3 * cscale + b1, h1, l1);
                *(u32*)(Ch + (size_t)m0 * ldc + n0) = h0;
                *(u32*)(Ch + (size_t)(m0 + 8) * ldc + n0) = h1;
                if (Cl) {
                    *(u32*)(Cl + (size_t)m0 * ldc + n0) = l0;
                    *(u32*)(Cl + (size_t)(m0 + 8) * ldc + n0) = l1;
                }
            } else { // MODE 2: exp -> fp16 hi; column sums of ROUNDED values
                __half e0 = __float2half_rn(__expf((c0 + mk0) * 0.125f));
                __half e1 = __float2half_rn(__expf((c1 + mk0) * 0.125f));
                __half e2 = __float2half_rn(__expf((c2 + mk8) * 0.125f));
                __half e3 = __float2half_rn(__expf((c3 + mk8) * 0.125f));
                __half2 p0; p0.x = e0; p0.y = e1;
                __half2 p1; p1.x = e2; p1.y = e3;
                *(u32*)(Ch + (size_t)m0 * ldc + n0) = *(u32*)&p0;
                *(u32*)(Ch + (size_t)(m0 + 8) * ldc + n0) = *(u32*)&p1;
                // sum over the 16 q-rows this warp's fragment covers
                float s0 = __half2float(e0) + __half2float(e2);
                float s1 = __half2float(e1) + __half2float(e3);
                s0 += __shfl_xor_sync(0xffffffffu, s0, 4);
                s0 += __shfl_xor_sync(0xffffffffu, s0, 8);
                s0 += __shfl_xor_sync(0xffffffffu, s0, 16);
                s1 += __shfl_xor_sync(0xffffffffu, s1, 4);
                s1 += __shfl_xor_sync(0xffffffffu, s1, 8);
                s1 += __shfl_xor_sync(0xffffffffu, s1, 16);
                if (lane < 4) {
                    atomicAdd(&g_sum[z * C_LEN + n0], s0);
                    atomicAdd(&g_sum[z * C_LEN + n0 + 1], s1);
                }
            }
        }
    }
}

// ------- V'' transpose+scale: vt[z][d][k] = V[z][k][d] * 2048 / sum[z][k] -------
// (x2048 keeps V'' O(1) in fp16; the exact 1/2048 is folded into the AV epilogue)
__global__ void __launch_bounds__(256) scale_v()
{
    __shared__ float t[32][33];
    const int z = blockIdx.z;
    const int k0 = blockIdx.x * 32, d0 = blockIdx.y * 32;
    const int tx = threadIdx.x & 31, ty = threadIdx.x >> 5;
    const size_t vbase = (size_t)z * (C_LEN * DV_);
#pragma unroll
    for (int i = 0; i < 4; i++)
        t[ty + i * 8][tx] = g_v[vbase + (size_t)(k0 + ty + i * 8) * DV_ + d0 + tx];
    __syncthreads();
    const float iv = 2048.0f / g_sum[z * C_LEN + k0 + tx];
#pragma unroll
    for (int i = 0; i < 4; i++) {
        float val = t[tx][ty + i * 8] * iv;
        size_t o = vbase + (size_t)(d0 + ty + i * 8) * C_LEN + k0 + tx;
        g_vt_h[o] = __float2half_rn(val);
    }
}

// ---------------------------------------------------------------------------
extern "C" void kernel_launch(void* const* d_in, const int* in_sizes, int n_in,
                              void* d_out, int out_size)
{
    const float* x    = (const float*)d_in[0];
    const float* mask = (const float*)d_in[1];
    const float* Mq_w = (const float*)d_in[2];
    const float* Mq_b = (const float*)d_in[3];
    const float* Mk_w = (const float*)d_in[4];
    const float* Mk_b = (const float*)d_in[5];
    const float* Mv_w = (const float*)d_in[6];
    const float* Mv_b = (const float*)d_in[7];
    const float* Wo_w = (const float*)d_in[8];
    const float* Wo_b = (const float*)d_in[9];
    float* out = (float*)d_out;

    __half *xs_h, *xs_l, *wq_h, *wk_h, *wv_h, *wo_h;
    __half *q_h, *q_l, *k_h, *e_h, *vt_h, *ao_h, *ao_l;
    float *v;
    cudaGetSymbolAddress((void**)&xs_h, g_xs_h); cudaGetSymbolAddress((void**)&xs_l, g_xs_l);
    cudaGetSymbolAddress((void**)&wq_h, g_wq_h);
    cudaGetSymbolAddress((void**)&wk_h, g_wk_h);
    cudaGetSymbolAddress((void**)&wv_h, g_wv_h);
    cudaGetSymbolAddress((void**)&wo_h, g_wo_h);
    cudaGetSymbolAddress((void**)&q_h,  g_q_h);  cudaGetSymbolAddress((void**)&q_l,  g_q_l);
    cudaGetSymbolAddress((void**)&k_h,  g_k_h);
    cudaGetSymbolAddress((void**)&e_h,  g_e_h);
    cudaGetSymbolAddress((void**)&vt_h, g_vt_h);
    cudaGetSymbolAddress((void**)&ao_h, g_ao_h); cudaGetSymbolAddress((void**)&ao_l, g_ao_l);
    cudaGetSymbolAddress((void**)&v,    g_v);

    dim3 blk(256);

    // splits: x -> hi+lo; weights -> hi only
    split_f32<<<(M_ROWS * DIN_ / 4 + 255) / 256, blk>>>(x, xs_h, xs_l, M_ROWS * DIN_ / 4);
    split_f32<<<(QK_COLS * DIN_ / 4 + 255) / 256, blk>>>(Mq_w, wq_h, nullptr, QK_COLS * DIN_ / 4);
    split_f32<<<(QK_COLS * DIN_ / 4 + 255) / 256, blk>>>(Mk_w, wk_h, nullptr, QK_COLS * DIN_ / 4);
    split_f32<<<(V_COLS * DIN_ / 4 + 255) / 256, blk>>>(Mv_w, wv_h, nullptr, V_COLS * DIN_ / 4);
    split_f32<<<(V_COLS * V_COLS / 4 + 255) / 256, blk>>>(Wo_w, wo_h, nullptr, V_COLS * V_COLS / 4);
    zero_sum<<<NZ * C_LEN / 256, blk>>>();

    // Q projection -> split fp16 (Q is the split operand of the scores GEMM)
    gemm_h2<1, 2><<<dim3(QK_COLS / 128, M_ROWS / 128, 1), blk>>>(
        xs_h, xs_l, wq_h, Mq_b, nullptr, 1.0f, nullptr, q_h, q_l,
        DIN_, DIN_, DIN_, QK_COLS, 0, 0, 0);
    // K projection -> fp16 hi only
    gemm_h2<1, 2><<<dim3(QK_COLS / 128, M_ROWS / 128, 1), blk>>>(
        xs_h, xs_l, wk_h, Mk_b, nullptr, 1.0f, nullptr, k_h, nullptr,
        DIN_, DIN_, DIN_, QK_COLS, 0, 0, 0);
    // V projection -> fp32
    gemm_h2<0, 2><<<dim3(V_COLS / 128, M_ROWS / 128, 1), blk>>>(
        xs_h, xs_l, wv_h, Mv_b, nullptr, 1.0f, v, nullptr, nullptr,
        DIN_, DIN_, DIN_, V_COLS, 0, 0, 0);

    // scores -> E = exp((QK^T+mask)/8) fp16 hi + column sums, batched over z
    gemm_h2<2, 2><<<dim3(C_LEN / 128, C_LEN / 128, NZ), blk>>>(
        q_h, q_l, k_h, nullptr, mask, 1.0f, nullptr, e_h, nullptr,
        DK_, DK_, DK_, C_LEN,
        (size_t)C_LEN * DK_, (size_t)C_LEN * DK_, (size_t)C_LEN * C_LEN);

    // V'' = V*2048/sum, transposed to [z][d][k], fp16 hi only
    scale_v<<<dim3(C_LEN / 32, DV_ / 32, NZ), blk>>>();

    // AO = (E @ V''^T) / 2048, split fp16 out — SINGLE-term E operand
    gemm_h2<1, 1><<<dim3(DV_ / 128, C_LEN / 128, NZ), blk>>>(
        e_h, nullptr, vt_h, nullptr, nullptr, 1.0f / 2048.0f, nullptr, ao_h, ao_l,
        C_LEN, C_LEN, C_LEN, DV_,
        (size_t)C_LEN * C_LEN, (size_t)C_LEN * DV_, (size_t)C_LEN * DV_);

    // out projection -> d_out fp32
    gemm_h2<0, 2><<<dim3(V_COLS / 128, M_ROWS / 128, 1), blk>>>(
        ao_h, ao_l, wo_h, Wo_b, nullptr, 1.0f, out, nullptr, nullptr,
        V_COLS, V_COLS, V_COLS, V_COLS, 0, 0, 0);
}

// round 9
// speedup vs baseline: 4.3938x; 1.0993x over previous
#include <cuda_runtime.h>
#include <cuda_fp16.h>
#include <cstdint>

#define B_SZ   4
#define C_LEN  2048
#define H_N    8
#define DK_    64
#define DV_    128
#define DIN_   1024
#define QK_COLS 512
#define V_COLS  1024
#define M_ROWS  8192
#define NZ      32

typedef unsigned int u32;
typedef unsigned short u16;

// ----------------------- device scratch (no allocs) -----------------------
__device__ __align__(16) __half g_xs_h[M_ROWS * DIN_];
__device__ __align__(16) __half g_xs_l[M_ROWS * DIN_];
__device__ __align__(16) __half g_wq_h[QK_COLS * DIN_];
__device__ __align__(16) __half g_wk_h[QK_COLS * DIN_];
__device__ __align__(16) __half g_wv_h[V_COLS * DIN_];
__device__ __align__(16) __half g_wo_h[V_COLS * V_COLS];
__device__ __align__(16) __half g_q_h[M_ROWS * QK_COLS];
__device__ __align__(16) __half g_k_h[M_ROWS * QK_COLS];
__device__ __align__(16) __half g_e_h[(size_t)NZ * C_LEN * C_LEN];  // 256MB
__device__ __align__(16) float  g_v [M_ROWS * V_COLS];
__device__ __align__(16) __half g_vt_h[M_ROWS * V_COLS];
__device__ __align__(16) __half g_ao_h[M_ROWS * V_COLS];
__device__ float g_sum[NZ * C_LEN];

// ----------------------- helpers -----------------------
__device__ __forceinline__ u32 smem_u32(const void* p) {
    return (u32)__cvta_generic_to_shared(p);
}
__device__ __forceinline__ void ldsm4(u32* r, u32 a) {
    asm volatile("ldmatrix.sync.aligned.m8n8.x4.shared.b16 {%0,%1,%2,%3}, [%4];\n"
                 : "=r"(r[0]), "=r"(r[1]), "=r"(r[2]), "=r"(r[3]) : "r"(a));
}
__device__ __forceinline__ void mma16816(float* d, const u32* a, u32 b0, u32 b1) {
    asm volatile(
        "mma.sync.aligned.m16n8k16.row.col.f32.f16.f16.f32 "
        "{%0,%1,%2,%3},{%4,%5,%6,%7},{%8,%9},{%0,%1,%2,%3};\n"
        : "+f"(d[0]), "+f"(d[1]), "+f"(d[2]), "+f"(d[3])
        : "r"(a[0]), "r"(a[1]), "r"(a[2]), "r"(a[3]), "r"(b0), "r"(b1));
}
// split (a,b) -> packed fp16x2 hi and lo
__device__ __forceinline__ void pack_split(float a, float b, u32& hi, u32& lo) {
    __half ha = __float2half_rn(a), hb = __float2half_rn(b);
    __half la = __float2half_rn(a - __half2float(ha));
    __half lb = __float2half_rn(b - __half2float(hb));
    __half2 hp; hp.x = ha; hp.y = hb;
    __half2 lp; lp.x = la; lp.y = lb;
    hi = *(u32*)&hp; lo = *(u32*)&lp;
}
#define CP16(dst, src) asm volatile("cp.async.cg.shared.global [%0], [%1], 16;\n" :: "r"(dst), "l"(src))
#define CPCOMMIT()     asm volatile("cp.async.commit_group;\n")
#define CPWAIT(n)      asm volatile("cp.async.wait_group %0;\n" :: "n"(n))

// ----------------------- fp32 -> fp16 hi/lo split (lo optional) -----------------------
__global__ void __launch_bounds__(256) split_f32(
    const float* __restrict__ src, __half* __restrict__ h,
    __half* __restrict__ l, int n4)
{
    int i = blockIdx.x * 256 + threadIdx.x;
    if (i >= n4) return;
    float4 v = ((const float4*)src)[i];
    u32 h0, l0, h1, l1;
    pack_split(v.x, v.y, h0, l0);
    pack_split(v.z, v.w, h1, l1);
    uint2 hh; hh.x = h0; hh.y = h1;
    ((uint2*)h)[i] = hh;
    if (l) {
        uint2 ll; ll.x = l0; ll.y = l1;
        ((uint2*)l)[i] = ll;
    }
}

__global__ void zero_sum() { g_sum[blockIdx.x * 256 + threadIdx.x] = 0.f; }

// ---------------------------------------------------------------------------
// fp16 NT GEMM: C = A@B^T; acc = AhBh (+ AlBh if TERMS==2).
// BM=128, BN=128, BK=16. 256 thr = 8 warps (4m x 2n), warp tile 32x64.
// cp.async double buffer. MODE 0: fp32 out = acc*cscale + bias.
// MODE 1: fp16 hi out = acc*cscale (+bias); lo also written iff Cl != null.
// MODE 2: E = exp((acc + mask[q])/8) -> fp16 hi out + column sums of the
//         ROUNDED values (exact renormalization downstream).
// ---------------------------------------------------------------------------
#define STG (128 * 24)   // u16 per tile stage
template <int MODE, int TERMS>
__global__ void __launch_bounds__(256) gemm_h2(
    const __half* __restrict__ Ah, const __half* __restrict__ Al,
    const __half* __restrict__ Bh,
    const float* __restrict__ bias, const float* __restrict__ mask, float cscale,
    float* __restrict__ Cf, __half* __restrict__ Ch, __half* __restrict__ Cl,
    int K, int lda, int ldb, int ldc,
    size_t sA, size_t sB, size_t sC)
{
    __shared__ __align__(16) u16 sAh[2][STG];
    __shared__ __align__(16) u16 sAl[TERMS == 2 ? 2 : 1][STG];
    __shared__ __align__(16) u16 sBh[2][STG];

    const int tid = threadIdx.x;
    const int lane = tid & 31, wid = tid >> 5;
    const int wm = wid & 3, wn = wid >> 2;
    const int bm = blockIdx.y * 128, bn = blockIdx.x * 128;
    const int z = blockIdx.z;

    Ah += sA * z; Bh += sB * z;
    if (TERMS == 2) Al += sA * z;
    if (Cf) Cf += sC * z;
    if (Ch) Ch += sC * z;
    if (Cl) Cl += sC * z;

    // staging: each thread copies one 16B piece per tile
    const int arow = tid >> 1, acol = (tid & 1) * 8;
    const size_t aoff = (size_t)(bm + arow) * lda + acol;
    const size_t boff = (size_t)(bn + arow) * ldb + acol;
    const u32 dAh = smem_u32(&sAh[0][arow * 24 + acol]);
    const u32 dAl = smem_u32(&sAl[0][arow * 24 + acol]);
    const u32 dBh = smem_u32(&sBh[0][arow * 24 + acol]);

    // ldmatrix base addresses (stage 0)
    const int grp = lane >> 3, l8 = lane & 7;
    const int amr = ((grp & 1) << 3) + l8, amc = (grp >> 1) << 3;
    const int bmr = ((grp >> 1) << 3) + l8, bmc = (grp & 1) << 3;
    u32 aH_ad[2], aL_ad[2], bH_ad[4];
#pragma unroll
    for (int mi = 0; mi < 2; mi++) {
        int r = wm * 32 + mi * 16 + amr;
        aH_ad[mi] = smem_u32(&sAh[0][r * 24 + amc]);
        aL_ad[mi] = smem_u32(&sAl[0][r * 24 + amc]);
    }
#pragma unroll
    for (int p = 0; p < 4; p++) {
        int r = wn * 64 + p * 16 + bmr;
        bH_ad[p] = smem_u32(&sBh[0][r * 24 + bmc]);
    }

    float acc[2][8][4] = {};
    const int NC = K >> 4;

    auto stage = [&](int buf, int c) {
        const u32 so = buf * (STG * 2);
        const size_t k0 = (size_t)c << 4;
        CP16(dAh + so, Ah + aoff + k0);
        if (TERMS == 2) CP16(dAl + so, Al + aoff + k0);
        CP16(dBh + so, Bh + boff + k0);
    };

    stage(0, 0); CPCOMMIT();

    for (int c = 0; c < NC; ++c) {
        const int buf = c & 1;
        if (c + 1 < NC) { stage(buf ^ 1, c + 1); CPCOMMIT(); CPWAIT(1); }
        else CPWAIT(0);
        __syncthreads();

        const u32 so = buf * (STG * 2);
        u32 aH[2][4], aL[2][4], bH[4][4];
#pragma unroll
        for (int mi = 0; mi < 2; mi++) {
            ldsm4(aH[mi], aH_ad[mi] + so);
            if (TERMS == 2) ldsm4(aL[mi], aL_ad[mi] + so);
        }
#pragma unroll
        for (int p = 0; p < 4; p++)
            ldsm4(bH[p], bH_ad[p] + so);
#pragma unroll
        for (int mi = 0; mi < 2; mi++)
#pragma unroll
            for (int ni = 0; ni < 8; ni++) {
                const int p = ni >> 1, q = (ni & 1) * 2;
                mma16816(acc[mi][ni], aH[mi], bH[p][q], bH[p][q + 1]);
                if (TERMS == 2)
                    mma16816(acc[mi][ni], aL[mi], bH[p][q], bH[p][q + 1]);
            }
        __syncthreads();
    }

    // ----------------- epilogue -----------------
    const int lr = lane >> 2, lc2 = (lane & 3) * 2;
#pragma unroll
    for (int mi = 0; mi < 2; mi++) {
        const int m0 = bm + wm * 32 + mi * 16 + lr;
        float mk0 = 0.f, mk8 = 0.f;
        if (MODE == 2) {
            const float* mrow = mask + (size_t)(z >> 3) * C_LEN;
            mk0 = mrow[m0]; mk8 = mrow[m0 + 8];
        }
#pragma unroll
        for (int ni = 0; ni < 8; ni++) {
            const int n0 = bn + wn * 64 + ni * 8 + lc2;
            float c0 = acc[mi][ni][0], c1 = acc[mi][ni][1];
            float c2 = acc[mi][ni][2], c3 = acc[mi][ni][3];
            if (MODE == 0) {
                float b0 = bias[n0], b1 = bias[n0 + 1];
                float2 r0; r0.x = c0 * cscale + b0; r0.y = c1 * cscale + b1;
                float2 r1; r1.x = c2 * cscale + b0; r1.y = c3 * cscale + b1;
                *(float2*)(Cf + (size_t)m0 * ldc + n0) = r0;
                *(float2*)(Cf + (size_t)(m0 + 8) * ldc + n0) = r1;
            } else if (MODE == 1) {
                float b0 = 0.f, b1 = 0.f;
                if (bias) { b0 = bias[n0]; b1 = bias[n0 + 1]; }
                u32 h0, l0, h1, l1;
                pack_split(c0 * cscale + b0, c1 * cscale + b1, h0, l0);
                pack_split(c2 * cscale + b0, c3 * cscale + b1, h1, l1);
                *(u32*)(Ch + (size_t)m0 * ldc + n0) = h0;
                *(u32*)(Ch + (size_t)(m0 + 8) * ldc + n0) = h1;
                if (Cl) {
                    *(u32*)(Cl + (size_t)m0 * ldc + n0) = l0;
                    *(u32*)(Cl + (size_t)(m0 + 8) * ldc + n0) = l1;
                }
            } else { // MODE 2: exp -> fp16 hi; column sums of ROUNDED values
                __half e0 = __float2half_rn(__expf((c0 + mk0) * 0.125f));
                __half e1 = __float2half_rn(__expf((c1 + mk0) * 0.125f));
                __half e2 = __float2half_rn(__expf((c2 + mk8) * 0.125f));
                __half e3 = __float2half_rn(__expf((c3 + mk8) * 0.125f));
                __half2 p0; p0.x = e0; p0.y = e1;
                __half2 p1; p1.x = e2; p1.y = e3;
                *(u32*)(Ch + (size_t)m0 * ldc + n0) = *(u32*)&p0;
                *(u32*)(Ch + (size_t)(m0 + 8) * ldc + n0) = *(u32*)&p1;
                // sum over the 16 q-rows this warp's fragment covers
                float s0 = __half2float(e0) + __half2float(e2);
                float s1 = __half2float(e1) + __half2float(e3);
                s0 += __shfl_xor_sync(0xffffffffu, s0, 4);
                s0 += __shfl_xor_sync(0xffffffffu, s0, 8);
                s0 += __shfl_xor_sync(0xffffffffu, s0, 16);
                s1 += __shfl_xor_sync(0xffffffffu, s1, 4);
                s1 += __shfl_xor_sync(0xffffffffu, s1, 8);
                s1 += __shfl_xor_sync(0xffffffffu, s1, 16);
                if (lane < 4) {
                    atomicAdd(&g_sum[z * C_LEN + n0], s0);
                    atomicAdd(&g_sum[z * C_LEN + n0 + 1], s1);
                }
            }
        }
    }
}

// ------- V'' transpose+scale: vt[z][d][k] = V[z][k][d] * 2048 / sum[z][k] -------
// (x2048 keeps V'' O(1) in fp16; the exact 1/2048 is folded into the AV epilogue)
__global__ void __launch_bounds__(256) scale_v()
{
    __shared__ float t[32][33];
    const int z = blockIdx.z;
    const int k0 = blockIdx.x * 32, d0 = blockIdx.y * 32;
    const int tx = threadIdx.x & 31, ty = threadIdx.x >> 5;
    const size_t vbase = (size_t)z * (C_LEN * DV_);
#pragma unroll
    for (int i = 0; i < 4; i++)
        t[ty + i * 8][tx] = g_v[vbase + (size_t)(k0 + ty + i * 8) * DV_ + d0 + tx];
    __syncthreads();
    const float iv = 2048.0f / g_sum[z * C_LEN + k0 + tx];
#pragma unroll
    for (int i = 0; i < 4; i++) {
        float val = t[tx][ty + i * 8] * iv;
        size_t o = vbase + (size_t)(d0 + ty + i * 8) * C_LEN + k0 + tx;
        g_vt_h[o] = __float2half_rn(val);
    }
}

// ---------------------------------------------------------------------------
extern "C" void kernel_launch(void* const* d_in, const int* in_sizes, int n_in,
                              void* d_out, int out_size)
{
    const float* x    = (const float*)d_in[0];
    const float* mask = (const float*)d_in[1];
    const float* Mq_w = (const float*)d_in[2];
    const float* Mq_b = (const float*)d_in[3];
    const float* Mk_w = (const float*)d_in[4];
    const float* Mk_b = (const float*)d_in[5];
    const float* Mv_w = (const float*)d_in[6];
    const float* Mv_b = (const float*)d_in[7];
    const float* Wo_w = (const float*)d_in[8];
    const float* Wo_b = (const float*)d_in[9];
    float* out = (float*)d_out;

    __half *xs_h, *xs_l, *wq_h, *wk_h, *wv_h, *wo_h;
    __half *q_h, *k_h, *e_h, *vt_h, *ao_h;
    float *v;
    cudaGetSymbolAddress((void**)&xs_h, g_xs_h); cudaGetSymbolAddress((void**)&xs_l, g_xs_l);
    cudaGetSymbolAddress((void**)&wq_h, g_wq_h);
    cudaGetSymbolAddress((void**)&wk_h, g_wk_h);
    cudaGetSymbolAddress((void**)&wv_h, g_wv_h);
    cudaGetSymbolAddress((void**)&wo_h, g_wo_h);
    cudaGetSymbolAddress((void**)&q_h,  g_q_h);
    cudaGetSymbolAddress((void**)&k_h,  g_k_h);
    cudaGetSymbolAddress((void**)&e_h,  g_e_h);
    cudaGetSymbolAddress((void**)&vt_h, g_vt_h);
    cudaGetSymbolAddress((void**)&ao_h, g_ao_h);
    cudaGetSymbolAddress((void**)&v,    g_v);

    dim3 blk(256);

    // splits: x -> hi+lo; weights -> hi only
    split_f32<<<(M_ROWS * DIN_ / 4 + 255) / 256, blk>>>(x, xs_h, xs_l, M_ROWS * DIN_ / 4);
    split_f32<<<(QK_COLS * DIN_ / 4 + 255) / 256, blk>>>(Mq_w, wq_h, nullptr, QK_COLS * DIN_ / 4);
    split_f32<<<(QK_COLS * DIN_ / 4 + 255) / 256, blk>>>(Mk_w, wk_h, nullptr, QK_COLS * DIN_ / 4);
    split_f32<<<(V_COLS * DIN_ / 4 + 255) / 256, blk>>>(Mv_w, wv_h, nullptr, V_COLS * DIN_ / 4);
    split_f32<<<(V_COLS * V_COLS / 4 + 255) / 256, blk>>>(Wo_w, wo_h, nullptr, V_COLS * V_COLS / 4);
    zero_sum<<<NZ * C_LEN / 256, blk>>>();

    // Q projection -> fp16 hi only (2-term in x)
    gemm_h2<1, 2><<<dim3(QK_COLS / 128, M_ROWS / 128, 1), blk>>>(
        xs_h, xs_l, wq_h, Mq_b, nullptr, 1.0f, nullptr, q_h, nullptr,
        DIN_, DIN_, DIN_, QK_COLS, 0, 0, 0);
    // K projection -> fp16 hi only
    gemm_h2<1, 2><<<dim3(QK_COLS / 128, M_ROWS / 128, 1), blk>>>(
        xs_h, xs_l, wk_h, Mk_b, nullptr, 1.0f, nullptr, k_h, nullptr,
        DIN_, DIN_, DIN_, QK_COLS, 0, 0, 0);
    // V projection -> fp32
    gemm_h2<0, 2><<<dim3(V_COLS / 128, M_ROWS / 128, 1), blk>>>(
        xs_h, xs_l, wv_h, Mv_b, nullptr, 1.0f, v, nullptr, nullptr,
        DIN_, DIN_, DIN_, V_COLS, 0, 0, 0);

    // scores -> E = exp((QK^T+mask)/8) fp16 hi + column sums; 1-term Q
    gemm_h2<2, 1><<<dim3(C_LEN / 128, C_LEN / 128, NZ), blk>>>(
        q_h, nullptr, k_h, nullptr, mask, 1.0f, nullptr, e_h, nullptr,
        DK_, DK_, DK_, C_LEN,
        (size_t)C_LEN * DK_, (size_t)C_LEN * DK_, (size_t)C_LEN * C_LEN);

    // V'' = V*2048/sum, transposed to [z][d][k], fp16 hi only
    scale_v<<<dim3(C_LEN / 32, DV_ / 32, NZ), blk>>>();

    // AO = (E @ V''^T) / 2048, fp16 hi out — 1-term E
    gemm_h2<1, 1><<<dim3(DV_ / 128, C_LEN / 128, NZ), blk>>>(
        e_h, nullptr, vt_h, nullptr, nullptr, 1.0f / 2048.0f, nullptr, ao_h, nullptr,
        C_LEN, C_LEN, C_LEN, DV_,
        (size_t)C_LEN * C_LEN, (size_t)C_LEN * DV_, (size_t)C_LEN * DV_);

    // out projection -> d_out fp32 — 1-term AO
    gemm_h2<0, 1><<<dim3(V_COLS / 128, M_ROWS / 128, 1), blk>>>(
        ao_h, nullptr, wo_h, Wo_b, nullptr, 1.0f, out, nullptr, nullptr,
        V_COLS, V_COLS, V_COLS, V_COLS, 0, 0, 0);
}

// round 10
// speedup vs baseline: 6.1512x; 1.4000x over previous
#include <cuda_runtime.h>
#include <cuda_fp16.h>
#include <cstdint>

#define B_SZ   4
#define C_LEN  2048
#define H_N    8
#define DK_    64
#define DV_    128
#define DIN_   1024
#define QK_COLS 512
#define V_COLS  1024
#define M_ROWS  8192
#define NZ      32

typedef unsigned int u32;
typedef unsigned short u16;

// ----------------------- device scratch (no allocs) -----------------------
__device__ __align__(16) __half g_xs_h[M_ROWS * DIN_];
__device__ __align__(16) __half g_wq_h[QK_COLS * DIN_];
__device__ __align__(16) __half g_wk_h[QK_COLS * DIN_];
__device__ __align__(16) __half g_wv_h[V_COLS * DIN_];
__device__ __align__(16) __half g_wo_h[V_COLS * V_COLS];
__device__ __align__(16) __half g_q_h[M_ROWS * QK_COLS];
__device__ __align__(16) __half g_k_h[M_ROWS * QK_COLS];
__device__ __align__(16) __half g_e_h[(size_t)NZ * C_LEN * C_LEN];  // 256MB
__device__ __align__(16) __half g_v_h[M_ROWS * V_COLS];
__device__ __align__(16) __half g_vt_h[M_ROWS * V_COLS];
__device__ __align__(16) __half g_ao_h[M_ROWS * V_COLS];
__device__ float g_sum[NZ * C_LEN];

// ----------------------- helpers -----------------------
__device__ __forceinline__ u32 smem_u32(const void* p) {
    return (u32)__cvta_generic_to_shared(p);
}
__device__ __forceinline__ void ldsm4(u32* r, u32 a) {
    asm volatile("ldmatrix.sync.aligned.m8n8.x4.shared.b16 {%0,%1,%2,%3}, [%4];\n"
                 : "=r"(r[0]), "=r"(r[1]), "=r"(r[2]), "=r"(r[3]) : "r"(a));
}
__device__ __forceinline__ void mma16816(float* d, const u32* a, u32 b0, u32 b1) {
    asm volatile(
        "mma.sync.aligned.m16n8k16.row.col.f32.f16.f16.f32 "
        "{%0,%1,%2,%3},{%4,%5,%6,%7},{%8,%9},{%0,%1,%2,%3};\n"
        : "+f"(d[0]), "+f"(d[1]), "+f"(d[2]), "+f"(d[3])
        : "r"(a[0]), "r"(a[1]), "r"(a[2]), "r"(a[3]), "r"(b0), "r"(b1));
}
__device__ __forceinline__ void pack_split(float a, float b, u32& hi, u32& lo) {
    __half ha = __float2half_rn(a), hb = __float2half_rn(b);
    __half la = __float2half_rn(a - __half2float(ha));
    __half lb = __float2half_rn(b - __half2float(hb));
    __half2 hp; hp.x = ha; hp.y = hb;
    __half2 lp; lp.x = la; lp.y = lb;
    hi = *(u32*)&hp; lo = *(u32*)&lp;
}
#define CP16(dst, src) asm volatile("cp.async.cg.shared.global [%0], [%1], 16;\n" :: "r"(dst), "l"(src))
#define CPCOMMIT()     asm volatile("cp.async.commit_group;\n")
#define CPWAIT(n)      asm volatile("cp.async.wait_group %0;\n" :: "n"(n))

// ----------------------- fp32 -> fp16 (hi only) -----------------------
__global__ void __launch_bounds__(256) split_f32(
    const float* __restrict__ src, __half* __restrict__ h, int n4)
{
    int i = blockIdx.x * 256 + threadIdx.x;
    if (i >= n4) return;
    float4 v = ((const float4*)src)[i];
    __half2 a; a.x = __float2half_rn(v.x); a.y = __float2half_rn(v.y);
    __half2 b; b.x = __float2half_rn(v.z); b.y = __float2half_rn(v.w);
    uint2 hh; hh.x = *(u32*)&a; hh.y = *(u32*)&b;
    ((uint2*)h)[i] = hh;
}

__global__ void zero_sum() { g_sum[blockIdx.x * 256 + threadIdx.x] = 0.f; }

// ---------------------------------------------------------------------------
// fp16 NT GEMM: C = A@B^T (single term).
// BM=128, BN=128, BK=32. 256 thr = 8 warps (4m x 2n), warp tile 32x64.
// cp.async double buffer; 32 HMMA/warp between syncs.
// MODE 0: fp32 out = acc*cscale + bias.
// MODE 1: fp16 out = acc*cscale (+bias).
// MODE 2: E = exp((acc + mask[q])/8) -> fp16 out + column sums of ROUNDED E.
// ---------------------------------------------------------------------------
#define STG (128 * 40)     // u16 per tile: 32 data + 8 pad per row (80B stride)
#define STGB (STG * 2)     // bytes per tile buffer step
template <int MODE>
__global__ void __launch_bounds__(256) gemm_h2(
    const __half* __restrict__ Ah, const __half* __restrict__ Bh,
    const float* __restrict__ bias, const float* __restrict__ mask, float cscale,
    float* __restrict__ Cf, __half* __restrict__ Ch,
    int K, int lda, int ldb, int ldc,
    size_t sA, size_t sB, size_t sC)
{
    __shared__ __align__(16) u16 sAs[2][STG];
    __shared__ __align__(16) u16 sBs[2][STG];

    const int tid = threadIdx.x;
    const int lane = tid & 31, wid = tid >> 5;
    const int wm = wid & 3, wn = wid >> 2;
    const int bm = blockIdx.y * 128, bn = blockIdx.x * 128;
    const int z = blockIdx.z;

    Ah += sA * z; Bh += sB * z;
    if (Cf) Cf += sC * z;
    if (Ch) Ch += sC * z;

    // staging: each thread copies two 16B pieces per tile (512 pieces total)
    const int r0 = tid >> 2,        c0 = (tid & 3) * 8;
    const int r1 = 64 + (tid >> 2), c1 = c0;
    const size_t aoff0 = (size_t)(bm + r0) * lda + c0;
    const size_t aoff1 = (size_t)(bm + r1) * lda + c1;
    const size_t boff0 = (size_t)(bn + r0) * ldb + c0;
    const size_t boff1 = (size_t)(bn + r1) * ldb + c1;
    const u32 dA0 = smem_u32(&sAs[0][r0 * 40 + c0]);
    const u32 dA1 = smem_u32(&sAs[0][r1 * 40 + c1]);
    const u32 dB0 = smem_u32(&sBs[0][r0 * 40 + c0]);
    const u32 dB1 = smem_u32(&sBs[0][r1 * 40 + c1]);

    // ldmatrix base addresses (stage 0, k-step 0)
    const int grp = lane >> 3, l8 = lane & 7;
    const int amr = ((grp & 1) << 3) + l8, amc = (grp >> 1) << 3;
    const int bmr = ((grp >> 1) << 3) + l8, bmc = (grp & 1) << 3;
    u32 aH_ad[2], bH_ad[4];
#pragma unroll
    for (int mi = 0; mi < 2; mi++)
        aH_ad[mi] = smem_u32(&sAs[0][(wm * 32 + mi * 16 + amr) * 40 + amc]);
#pragma unroll
    for (int p = 0; p < 4; p++)
        bH_ad[p] = smem_u32(&sBs[0][(wn * 64 + p * 16 + bmr) * 40 + bmc]);

    float acc[2][8][4] = {};
    const int NC = K >> 5;

    auto stage = [&](int buf, int c) {
        const u32 so = buf * STGB;
        const size_t k0 = (size_t)c << 5;
        CP16(dA0 + so, Ah + aoff0 + k0);
        CP16(dA1 + so, Ah + aoff1 + k0);
        CP16(dB0 + so, Bh + boff0 + k0);
        CP16(dB1 + so, Bh + boff1 + k0);
    };

    stage(0, 0); CPCOMMIT();

    for (int c = 0; c < NC; ++c) {
        const int buf = c & 1;
        if (c + 1 < NC) { stage(buf ^ 1, c + 1); CPCOMMIT(); CPWAIT(1); }
        else CPWAIT(0);
        __syncthreads();

        const u32 so = buf * STGB;
#pragma unroll
        for (int s = 0; s < 2; s++) {
            const u32 ko = so + s * 32;   // +16 elems = +32 bytes
            u32 aH[2][4], bH[4][4];
            ldsm4(aH[0], aH_ad[0] + ko);
            ldsm4(aH[1], aH_ad[1] + ko);
#pragma unroll
            for (int p = 0; p < 4; p++)
                ldsm4(bH[p], bH_ad[p] + ko);
#pragma unroll
            for (int mi = 0; mi < 2; mi++)
#pragma unroll
                for (int ni = 0; ni < 8; ni++) {
                    const int p = ni >> 1, q = (ni & 1) * 2;
                    mma16816(acc[mi][ni], aH[mi], bH[p][q], bH[p][q + 1]);
                }
        }
        __syncthreads();
    }

    // ----------------- epilogue -----------------
    const int lr = lane >> 2, lc2 = (lane & 3) * 2;
#pragma unroll
    for (int mi = 0; mi < 2; mi++) {
        const int m0 = bm + wm * 32 + mi * 16 + lr;
        float mk0 = 0.f, mk8 = 0.f;
        if (MODE == 2) {
            const float* mrow = mask + (size_t)(z >> 3) * C_LEN;
            mk0 = mrow[m0]; mk8 = mrow[m0 + 8];
        }
#pragma unroll
        for (int ni = 0; ni < 8; ni++) {
            const int n0 = bn + wn * 64 + ni * 8 + lc2;
            float c0 = acc[mi][ni][0], c1 = acc[mi][ni][1];
            float c2 = acc[mi][ni][2], c3 = acc[mi][ni][3];
            if (MODE == 0) {
                float b0 = bias[n0], b1 = bias[n0 + 1];
                float2 o0; o0.x = c0 * cscale + b0; o0.y = c1 * cscale + b1;
                float2 o1; o1.x = c2 * cscale + b0; o1.y = c3 * cscale + b1;
                *(float2*)(Cf + (size_t)m0 * ldc + n0) = o0;
                *(float2*)(Cf + (size_t)(m0 + 8) * ldc + n0) = o1;
            } else if (MODE == 1) {
                float b0 = 0.f, b1 = 0.f;
                if (bias) { b0 = bias[n0]; b1 = bias[n0 + 1]; }
                __half2 p0, p1;
                p0.x = __float2half_rn(c0 * cscale + b0);
                p0.y = __float2half_rn(c1 * cscale + b1);
                p1.x = __float2half_rn(c2 * cscale + b0);
                p1.y = __float2half_rn(c3 * cscale + b1);
                *(u32*)(Ch + (size_t)m0 * ldc + n0) = *(u32*)&p0;
                *(u32*)(Ch + (size_t)(m0 + 8) * ldc + n0) = *(u32*)&p1;
            } else { // MODE 2: exp -> fp16; column sums of ROUNDED values
                __half e0 = __float2half_rn(__expf((c0 + mk0) * 0.125f));
                __half e1 = __float2half_rn(__expf((c1 + mk0) * 0.125f));
                __half e2 = __float2half_rn(__expf((c2 + mk8) * 0.125f));
                __half e3 = __float2half_rn(__expf((c3 + mk8) * 0.125f));
                __half2 p0; p0.x = e0; p0.y = e1;
                __half2 p1; p1.x = e2; p1.y = e3;
                *(u32*)(Ch + (size_t)m0 * ldc + n0) = *(u32*)&p0;
                *(u32*)(Ch + (size_t)(m0 + 8) * ldc + n0) = *(u32*)&p1;
                float s0 = __half2float(e0) + __half2float(e2);
                float s1 = __half2float(e1) + __half2float(e3);
                s0 += __shfl_xor_sync(0xffffffffu, s0, 4);
                s0 += __shfl_xor_sync(0xffffffffu, s0, 8);
                s0 += __shfl_xor_sync(0xffffffffu, s0, 16);
                s1 += __shfl_xor_sync(0xffffffffu, s1, 4);
                s1 += __shfl_xor_sync(0xffffffffu, s1, 8);
                s1 += __shfl_xor_sync(0xffffffffu, s1, 16);
                if (lane < 4) {
                    atomicAdd(&g_sum[z * C_LEN + n0], s0);
                    atomicAdd(&g_sum[z * C_LEN + n0 + 1], s1);
                }
            }
        }
    }
}

// ------- V'' transpose+scale: vt[z][d][k] = V[z][k][d] * 2048 / sum[z][k] -------
__global__ void __launch_bounds__(256) scale_v()
{
    __shared__ float t[32][33];
    const int z = blockIdx.z;
    const int k0 = blockIdx.x * 32, d0 = blockIdx.y * 32;
    const int tx = threadIdx.x & 31, ty = threadIdx.x >> 5;
    const size_t vbase = (size_t)z * (C_LEN * DV_);
#pragma unroll
    for (int i = 0; i < 4; i++)
        t[ty + i * 8][tx] = __half2float(
            g_v_h[vbase + (size_t)(k0 + ty + i * 8) * DV_ + d0 + tx]);
    __syncthreads();
    const float iv = 2048.0f / g_sum[z * C_LEN + k0 + tx];
#pragma unroll
    for (int i = 0; i < 4; i++) {
        float val = t[tx][ty + i * 8] * iv;
        size_t o = vbase + (size_t)(d0 + ty + i * 8) * C_LEN + k0 + tx;
        g_vt_h[o] = __float2half_rn(val);
    }
}

// ---------------------------------------------------------------------------
extern "C" void kernel_launch(void* const* d_in, const int* in_sizes, int n_in,
                              void* d_out, int out_size)
{
    const float* x    = (const float*)d_in[0];
    const float* mask = (const float*)d_in[1];
    const float* Mq_w = (const float*)d_in[2];
    const float* Mq_b = (const float*)d_in[3];
    const float* Mk_w = (const float*)d_in[4];
    const float* Mk_b = (const float*)d_in[5];
    const float* Mv_w = (const float*)d_in[6];
    const float* Mv_b = (const float*)d_in[7];
    const float* Wo_w = (const float*)d_in[8];
    const float* Wo_b = (const float*)d_in[9];
    float* out = (float*)d_out;

    __half *xs_h, *wq_h, *wk_h, *wv_h, *wo_h;
    __half *q_h, *k_h, *e_h, *v_h, *vt_h, *ao_h;
    cudaGetSymbolAddress((void**)&xs_h, g_xs_h);
    cudaGetSymbolAddress((void**)&wq_h, g_wq_h);
    cudaGetSymbolAddress((void**)&wk_h, g_wk_h);
    cudaGetSymbolAddress((void**)&wv_h, g_wv_h);
    cudaGetSymbolAddress((void**)&wo_h, g_wo_h);
    cudaGetSymbolAddress((void**)&q_h,  g_q_h);
    cudaGetSymbolAddress((void**)&k_h,  g_k_h);
    cudaGetSymbolAddress((void**)&e_h,  g_e_h);
    cudaGetSymbolAddress((void**)&v_h,  g_v_h);
    cudaGetSymbolAddress((void**)&vt_h, g_vt_h);
    cudaGetSymbolAddress((void**)&ao_h, g_ao_h);

    dim3 blk(256);

    split_f32<<<(M_ROWS * DIN_ / 4 + 255) / 256, blk>>>(x, xs_h, M_ROWS * DIN_ / 4);
    split_f32<<<(QK_COLS * DIN_ / 4 + 255) / 256, blk>>>(Mq_w, wq_h, QK_COLS * DIN_ / 4);
    split_f32<<<(QK_COLS * DIN_ / 4 + 255) / 256, blk>>>(Mk_w, wk_h, QK_COLS * DIN_ / 4);
    split_f32<<<(V_COLS * DIN_ / 4 + 255) / 256, blk>>>(Mv_w, wv_h, V_COLS * DIN_ / 4);
    split_f32<<<(V_COLS * V_COLS / 4 + 255) / 256, blk>>>(Wo_w, wo_h, V_COLS * V_COLS / 4);
    zero_sum<<<NZ * C_LEN / 256, blk>>>();

    // Q, K, V projections -> fp16
    gemm_h2<1><<<dim3(QK_COLS / 128, M_ROWS / 128, 1), blk>>>(
        xs_h, wq_h, Mq_b, nullptr, 1.0f, nullptr, q_h,
        DIN_, DIN_, DIN_, QK_COLS, 0, 0, 0);
    gemm_h2<1><<<dim3(QK_COLS / 128, M_ROWS / 128, 1), blk>>>(
        xs_h, wk_h, Mk_b, nullptr, 1.0f, nullptr, k_h,
        DIN_, DIN_, DIN_, QK_COLS, 0, 0, 0);
    gemm_h2<1><<<dim3(V_COLS / 128, M_ROWS / 128, 1), blk>>>(
        xs_h, wv_h, Mv_b, nullptr, 1.0f, nullptr, v_h,
        DIN_, DIN_, DIN_, V_COLS, 0, 0, 0);

    // scores -> E = exp((QK^T+mask)/8) fp16 + column sums, batched over z
    gemm_h2<2><<<dim3(C_LEN / 128, C_LEN / 128, NZ), blk>>>(
        q_h, k_h, nullptr, mask, 1.0f, nullptr, e_h,
        DK_, DK_, DK_, C_LEN,
        (size_t)C_LEN * DK_, (size_t)C_LEN * DK_, (size_t)C_LEN * C_LEN);

    // V'' = V*2048/sum, transposed to [z][d][k]
    scale_v<<<dim3(C_LEN / 32, DV_ / 32, NZ), blk>>>();

    // AO = (E @ V''^T) / 2048
    gemm_h2<1><<<dim3(DV_ / 128, C_LEN / 128, NZ), blk>>>(
        e_h, vt_h, nullptr, nullptr, 1.0f / 2048.0f, nullptr, ao_h,
        C_LEN, C_LEN, C_LEN, DV_,
        (size_t)C_LEN * C_LEN, (size_t)C_LEN * DV_, (size_t)C_LEN * DV_);

    // out projection -> d_out fp32
    gemm_h2<0><<<dim3(V_COLS / 128, M_ROWS / 128, 1), blk>>>(
        ao_h, wo_h, Wo_b, nullptr, 1.0f, out, nullptr,
        V_COLS, V_COLS, V_COLS, V_COLS, 0, 0, 0);
}

// round 11
// speedup vs baseline: 6.2450x; 1.0153x over previous
#include <cuda_runtime.h>
#include <cuda_fp16.h>
#include <cstdint>

#define B_SZ   4
#define C_LEN  2048
#define H_N    8
#define DK_    64
#define DV_    128
#define DIN_   1024
#define QK_COLS 512
#define V_COLS  1024
#define M_ROWS  8192
#define NZ      32

typedef unsigned int u32;
typedef unsigned short u16;

// ----------------------- device scratch (no allocs) -----------------------
__device__ __align__(16) __half g_xs_h[M_ROWS * DIN_];
__device__ __align__(16) __half g_wq_h[QK_COLS * DIN_];
__device__ __align__(16) __half g_wk_h[QK_COLS * DIN_];
__device__ __align__(16) __half g_wv_h[V_COLS * DIN_];
__device__ __align__(16) __half g_wo_h[V_COLS * V_COLS];
__device__ __align__(16) __half g_q_h[M_ROWS * QK_COLS];
__device__ __align__(16) __half g_k_h[M_ROWS * QK_COLS];
__device__ __align__(16) __half g_e_h[(size_t)NZ * C_LEN * C_LEN];  // 256MB
__device__ __align__(16) __half g_v_h[M_ROWS * V_COLS];
__device__ __align__(16) __half g_vt_h[M_ROWS * V_COLS];
__device__ __align__(16) __half g_ao_h[M_ROWS * V_COLS];
__device__ float g_sum[NZ * C_LEN];

// ----------------------- helpers -----------------------
__device__ __forceinline__ u32 smem_u32(const void* p) {
    return (u32)__cvta_generic_to_shared(p);
}
__device__ __forceinline__ void ldsm4(u32* r, u32 a) {
    asm volatile("ldmatrix.sync.aligned.m8n8.x4.shared.b16 {%0,%1,%2,%3}, [%4];\n"
                 : "=r"(r[0]), "=r"(r[1]), "=r"(r[2]), "=r"(r[3]) : "r"(a));
}
__device__ __forceinline__ void mma16816(float* d, const u32* a, u32 b0, u32 b1) {
    asm volatile(
        "mma.sync.aligned.m16n8k16.row.col.f32.f16.f16.f32 "
        "{%0,%1,%2,%3},{%4,%5,%6,%7},{%8,%9},{%0,%1,%2,%3};\n"
        : "+f"(d[0]), "+f"(d[1]), "+f"(d[2]), "+f"(d[3])
        : "r"(a[0]), "r"(a[1]), "r"(a[2]), "r"(a[3]), "r"(b0), "r"(b1));
}
// packed 2x exp2 in fp16: returns half2 {lo=2^lo_arg, hi=2^hi_arg}
__device__ __forceinline__ u32 exp2_h2(float lo, float hi) {
    u32 r;
    asm("{\n\t.reg .b32 t;\n\t"
        "cvt.rn.f16x2.f32 t, %1, %2;\n\t"
        "ex2.approx.f16x2 %0, t;\n\t}"
        : "=r"(r) : "f"(hi), "f"(lo));
    return r;
}
#define CP16(dst, src) asm volatile("cp.async.cg.shared.global [%0], [%1], 16;\n" :: "r"(dst), "l"(src))
#define CPCOMMIT()     asm volatile("cp.async.commit_group;\n")
#define CPWAIT(n)      asm volatile("cp.async.wait_group %0;\n" :: "n"(n))

// ----------------------- fp32 -> fp16 -----------------------
__global__ void __launch_bounds__(256) split_f32(
    const float* __restrict__ src, __half* __restrict__ h, int n4)
{
    int i = blockIdx.x * 256 + threadIdx.x;
    if (i >= n4) return;
    float4 v = ((const float4*)src)[i];
    __half2 a; a.x = __float2half_rn(v.x); a.y = __float2half_rn(v.y);
    __half2 b; b.x = __float2half_rn(v.z); b.y = __float2half_rn(v.w);
    uint2 hh; hh.x = *(u32*)&a; hh.y = *(u32*)&b;
    ((uint2*)h)[i] = hh;
}

__global__ void zero_sum() { g_sum[blockIdx.x * 256 + threadIdx.x] = 0.f; }

// ---------------------------------------------------------------------------
// fp16 NT GEMM: C = A@B^T. BM=128, BN=128, BK=32. 256 thr = 8 warps (4m x 2n).
// cp.async double buffer, ONE __syncthreads per chunk.
// MODE 0: fp32 out = acc*cscale + bias.
// MODE 1: fp16 out = acc*cscale (+bias).
// MODE 2: E = exp2((acc+mask[q])*log2e/8) via ex2.approx.f16x2 -> fp16 out +
//         column sums of the ROUNDED values (exact renormalization downstream).
// ---------------------------------------------------------------------------
#define STG (128 * 40)     // u16 per tile: 32 data + 8 pad per row (80B stride)
#define STGB (STG * 2)     // bytes per tile buffer step
template <int MODE>
__global__ void __launch_bounds__(256, 2) gemm_h2(
    const __half* __restrict__ Ah, const __half* __restrict__ Bh,
    const float* __restrict__ bias, const float* __restrict__ mask, float cscale,
    float* __restrict__ Cf, __half* __restrict__ Ch,
    int K, int lda, int ldb, int ldc,
    size_t sA, size_t sB, size_t sC)
{
    __shared__ __align__(16) u16 sAs[2][STG];
    __shared__ __align__(16) u16 sBs[2][STG];

    const int tid = threadIdx.x;
    const int lane = tid & 31, wid = tid >> 5;
    const int wm = wid & 3, wn = wid >> 2;
    const int bm = blockIdx.y * 128, bn = blockIdx.x * 128;
    const int z = blockIdx.z;

    Ah += sA * z; Bh += sB * z;
    if (Cf) Cf += sC * z;
    if (Ch) Ch += sC * z;

    // staging: each thread copies two 16B pieces per tile (512 pieces total)
    const int r0 = tid >> 2,        c0i = (tid & 3) * 8;
    const int r1 = 64 + (tid >> 2);
    const size_t aoff0 = (size_t)(bm + r0) * lda + c0i;
    const size_t aoff1 = (size_t)(bm + r1) * lda + c0i;
    const size_t boff0 = (size_t)(bn + r0) * ldb + c0i;
    const size_t boff1 = (size_t)(bn + r1) * ldb + c0i;
    const u32 dA0 = smem_u32(&sAs[0][r0 * 40 + c0i]);
    const u32 dA1 = smem_u32(&sAs[0][r1 * 40 + c0i]);
    const u32 dB0 = smem_u32(&sBs[0][r0 * 40 + c0i]);
    const u32 dB1 = smem_u32(&sBs[0][r1 * 40 + c0i]);

    // ldmatrix base addresses (stage 0, k-step 0)
    const int grp = lane >> 3, l8 = lane & 7;
    const int amr = ((grp & 1) << 3) + l8, amc = (grp >> 1) << 3;
    const int bmr = ((grp >> 1) << 3) + l8, bmc = (grp & 1) << 3;
    u32 aH_ad[2], bH_ad[4];
#pragma unroll
    for (int mi = 0; mi < 2; mi++)
        aH_ad[mi] = smem_u32(&sAs[0][(wm * 32 + mi * 16 + amr) * 40 + amc]);
#pragma unroll
    for (int p = 0; p < 4; p++)
        bH_ad[p] = smem_u32(&sBs[0][(wn * 64 + p * 16 + bmr) * 40 + bmc]);

    float acc[2][8][4] = {};
    const int NC = K >> 5;

    auto stage = [&](int buf, int c) {
        const u32 so = buf * STGB;
        const size_t k0 = (size_t)c << 5;
        CP16(dA0 + so, Ah + aoff0 + k0);
        CP16(dA1 + so, Ah + aoff1 + k0);
        CP16(dB0 + so, Bh + boff0 + k0);
        CP16(dB1 + so, Bh + boff1 + k0);
    };

    stage(0, 0); CPCOMMIT();

    for (int c = 0; c < NC; ++c) {
        const int buf = c & 1;
        CPWAIT(0);          // my copies for chunk c have landed
        __syncthreads();    // everyone's landed; buf^1 fully consumed (iter c-1)
        if (c + 1 < NC) { stage(buf ^ 1, c + 1); CPCOMMIT(); }

        const u32 so = buf * STGB;
#pragma unroll
        for (int s = 0; s < 2; s++) {
            const u32 ko = so + s * 32;   // +16 elems = +32 bytes
            u32 aH[2][4], bH[4][4];
            ldsm4(aH[0], aH_ad[0] + ko);
            ldsm4(aH[1], aH_ad[1] + ko);
#pragma unroll
            for (int p = 0; p < 4; p++)
                ldsm4(bH[p], bH_ad[p] + ko);
#pragma unroll
            for (int mi = 0; mi < 2; mi++)
#pragma unroll
                for (int ni = 0; ni < 8; ni++) {
                    const int p = ni >> 1, q = (ni & 1) * 2;
                    mma16816(acc[mi][ni], aH[mi], bH[p][q], bH[p][q + 1]);
                }
        }
    }

    // ----------------- epilogue -----------------
    const float K2E = 0.18033688011112042f;   // log2(e)/8
    const int lr = lane >> 2, lc2 = (lane & 3) * 2;
#pragma unroll
    for (int mi = 0; mi < 2; mi++) {
        const int m0 = bm + wm * 32 + mi * 16 + lr;
        float mkl0 = 0.f, mkl8 = 0.f;
        if (MODE == 2) {
            const float* mrow = mask + (size_t)(z >> 3) * C_LEN;
            mkl0 = mrow[m0] * K2E; mkl8 = mrow[m0 + 8] * K2E;
        }
#pragma unroll
        for (int ni = 0; ni < 8; ni++) {
            const int n0 = bn + wn * 64 + ni * 8 + lc2;
            float c0 = acc[mi][ni][0], c1 = acc[mi][ni][1];
            float c2 = acc[mi][ni][2], c3 = acc[mi][ni][3];
            if (MODE == 0) {
                float b0 = bias[n0], b1 = bias[n0 + 1];
                float2 o0; o0.x = c0 * cscale + b0; o0.y = c1 * cscale + b1;
                float2 o1; o1.x = c2 * cscale + b0; o1.y = c3 * cscale + b1;
                *(float2*)(Cf + (size_t)m0 * ldc + n0) = o0;
                *(float2*)(Cf + (size_t)(m0 + 8) * ldc + n0) = o1;
            } else if (MODE == 1) {
                float b0 = 0.f, b1 = 0.f;
                if (bias) { b0 = bias[n0]; b1 = bias[n0 + 1]; }
                __half2 p0, p1;
                p0.x = __float2half_rn(c0 * cscale + b0);
                p0.y = __float2half_rn(c1 * cscale + b1);
                p1.x = __float2half_rn(c2 * cscale + b0);
                p1.y = __float2half_rn(c3 * cscale + b1);
                *(u32*)(Ch + (size_t)m0 * ldc + n0) = *(u32*)&p0;
                *(u32*)(Ch + (size_t)(m0 + 8) * ldc + n0) = *(u32*)&p1;
            } else { // MODE 2: packed fp16 exp2 + store + column sums of stored values
                u32 p0 = exp2_h2(c0 * K2E + mkl0, c1 * K2E + mkl0);
                u32 p1 = exp2_h2(c2 * K2E + mkl8, c3 * K2E + mkl8);
                *(u32*)(Ch + (size_t)m0 * ldc + n0) = p0;
                *(u32*)(Ch + (size_t)(m0 + 8) * ldc + n0) = p1;
                __half2 h0 = *(__half2*)&p0, h1 = *(__half2*)&p1;
                float s0 = __half2float(h0.x) + __half2float(h1.x);
                float s1 = __half2float(h0.y) + __half2float(h1.y);
                s0 += __shfl_xor_sync(0xffffffffu, s0, 4);
                s0 += __shfl_xor_sync(0xffffffffu, s0, 8);
                s0 += __shfl_xor_sync(0xffffffffu, s0, 16);
                s1 += __shfl_xor_sync(0xffffffffu, s1, 4);
                s1 += __shfl_xor_sync(0xffffffffu, s1, 8);
                s1 += __shfl_xor_sync(0xffffffffu, s1, 16);
                if (lane < 4) {
                    atomicAdd(&g_sum[z * C_LEN + n0], s0);
                    atomicAdd(&g_sum[z * C_LEN + n0 + 1], s1);
                }
            }
        }
    }
}

// ------- V'' transpose+scale: vt[z][d][k] = V[z][k][d] * 2048 / sum[z][k] -------
__global__ void __launch_bounds__(256) scale_v()
{
    __shared__ float t[32][33];
    const int z = blockIdx.z;
    const int k0 = blockIdx.x * 32, d0 = blockIdx.y * 32;
    const int tx = threadIdx.x & 31, ty = threadIdx.x >> 5;
    const size_t vbase = (size_t)z * (C_LEN * DV_);
#pragma unroll
    for (int i = 0; i < 4; i++)
        t[ty + i * 8][tx] = __half2float(
            g_v_h[vbase + (size_t)(k0 + ty + i * 8) * DV_ + d0 + tx]);
    __syncthreads();
    const float iv = 2048.0f / g_sum[z * C_LEN + k0 + tx];
#pragma unroll
    for (int i = 0; i < 4; i++) {
        float val = t[tx][ty + i * 8] * iv;
        size_t o = vbase + (size_t)(d0 + ty + i * 8) * C_LEN + k0 + tx;
        g_vt_h[o] = __float2half_rn(val);
    }
}

// ---------------------------------------------------------------------------
extern "C" void kernel_launch(void* const* d_in, const int* in_sizes, int n_in,
                              void* d_out, int out_size)
{
    const float* x    = (const float*)d_in[0];
    const float* mask = (const float*)d_in[1];
    const float* Mq_w = (const float*)d_in[2];
    const float* Mq_b = (const float*)d_in[3];
    const float* Mk_w = (const float*)d_in[4];
    const float* Mk_b = (const float*)d_in[5];
    const float* Mv_w = (const float*)d_in[6];
    const float* Mv_b = (const float*)d_in[7];
    const float* Wo_w = (const float*)d_in[8];
    const float* Wo_b = (const float*)d_in[9];
    float* out = (float*)d_out;

    __half *xs_h, *wq_h, *wk_h, *wv_h, *wo_h;
    __half *q_h, *k_h, *e_h, *v_h, *vt_h, *ao_h;
    cudaGetSymbolAddress((void**)&xs_h, g_xs_h);
    cudaGetSymbolAddress((void**)&wq_h, g_wq_h);
    cudaGetSymbolAddress((void**)&wk_h, g_wk_h);
    cudaGetSymbolAddress((void**)&wv_h, g_wv_h);
    cudaGetSymbolAddress((void**)&wo_h, g_wo_h);
    cudaGetSymbolAddress((void**)&q_h,  g_q_h);
    cudaGetSymbolAddress((void**)&k_h,  g_k_h);
    cudaGetSymbolAddress((void**)&e_h,  g_e_h);
    cudaGetSymbolAddress((void**)&v_h,  g_v_h);
    cudaGetSymbolAddress((void**)&vt_h, g_vt_h);
    cudaGetSymbolAddress((void**)&ao_h, g_ao_h);

    dim3 blk(256);

    split_f32<<<(M_ROWS * DIN_ / 4 + 255) / 256, blk>>>(x, xs_h, M_ROWS * DIN_ / 4);
    split_f32<<<(QK_COLS * DIN_ / 4 + 255) / 256, blk>>>(Mq_w, wq_h, QK_COLS * DIN_ / 4);
    split_f32<<<(QK_COLS * DIN_ / 4 + 255) / 256, blk>>>(Mk_w, wk_h, QK_COLS * DIN_ / 4);
    split_f32<<<(V_COLS * DIN_ / 4 + 255) / 256, blk>>>(Mv_w, wv_h, V_COLS * DIN_ / 4);
    split_f32<<<(V_COLS * V_COLS / 4 + 255) / 256, blk>>>(Wo_w, wo_h, V_COLS * V_COLS / 4);
    zero_sum<<<NZ * C_LEN / 256, blk>>>();

    // Q, K, V projections -> fp16
    gemm_h2<1><<<dim3(QK_COLS / 128, M_ROWS / 128, 1), blk>>>(
        xs_h, wq_h, Mq_b, nullptr, 1.0f, nullptr, q_h,
        DIN_, DIN_, DIN_, QK_COLS, 0, 0, 0);
    gemm_h2<1><<<dim3(QK_COLS / 128, M_ROWS / 128, 1), blk>>>(
        xs_h, wk_h, Mk_b, nullptr, 1.0f, nullptr, k_h,
        DIN_, DIN_, DIN_, QK_COLS, 0, 0, 0);
    gemm_h2<1><<<dim3(V_COLS / 128, M_ROWS / 128, 1), blk>>>(
        xs_h, wv_h, Mv_b, nullptr, 1.0f, nullptr, v_h,
        DIN_, DIN_, DIN_, V_COLS, 0, 0, 0);

    // scores -> E = exp((QK^T+mask)/8) fp16 + column sums, batched over z
    gemm_h2<2><<<dim3(C_LEN / 128, C_LEN / 128, NZ), blk>>>(
        q_h, k_h, nullptr, mask, 1.0f, nullptr, e_h,
        DK_, DK_, DK_, C_LEN,
        (size_t)C_LEN * DK_, (size_t)C_LEN * DK_, (size_t)C_LEN * C_LEN);

    // V'' = V*2048/sum, transposed to [z][d][k]
    scale_v<<<dim3(C_LEN / 32, DV_ / 32, NZ), blk>>>();

    // AO = (E @ V''^T) / 2048
    gemm_h2<1><<<dim3(DV_ / 128, C_LEN / 128, NZ), blk>>>(
        e_h, vt_h, nullptr, nullptr, 1.0f / 2048.0f, nullptr, ao_h,
        C_LEN, C_LEN, C_LEN, DV_,
        (size_t)C_LEN * C_LEN, (size_t)C_LEN * DV_, (size_t)C_LEN * DV_);

    // out projection -> d_out fp32
    gemm_h2<0><<<dim3(V_COLS / 128, M_ROWS / 128, 1), blk>>>(
        ao_h, wo_h, Wo_b, nullptr, 1.0f, out, nullptr,
        V_COLS, V_COLS, V_COLS, V_COLS, 0, 0, 0);
}

// round 12
// speedup vs baseline: 6.4914x; 1.0394x over previous
#include <cuda_runtime.h>
#include <cuda_fp16.h>
#include <cstdint>

#define B_SZ   4
#define C_LEN  2048
#define H_N    8
#define DK_    64
#define DV_    128
#define DIN_   1024
#define QK_COLS 512
#define V_COLS  1024
#define M_ROWS  8192
#define NZ      32

typedef unsigned int u32;
typedef unsigned short u16;

// ----------------------- device scratch (no allocs) -----------------------
__device__ __align__(16) __half g_xs_h[M_ROWS * DIN_];
__device__ __align__(16) __half g_wq_h[QK_COLS * DIN_];
__device__ __align__(16) __half g_wk_h[QK_COLS * DIN_];
__device__ __align__(16) __half g_wv_h[V_COLS * DIN_];
__device__ __align__(16) __half g_wo_h[V_COLS * V_COLS];
__device__ __align__(16) __half g_q_h[M_ROWS * QK_COLS];
__device__ __align__(16) __half g_k_h[M_ROWS * QK_COLS];
__device__ __align__(16) __half g_e_h[(size_t)NZ * C_LEN * C_LEN];  // 256MB
__device__ __align__(16) __half g_v_h[M_ROWS * V_COLS];
__device__ __align__(16) __half g_vt_h[M_ROWS * V_COLS];
__device__ __align__(16) __half g_ao_h[M_ROWS * V_COLS];
__device__ __align__(16) float g_sum[NZ * C_LEN];

// ----------------------- helpers -----------------------
__device__ __forceinline__ u32 smem_u32(const void* p) {
    return (u32)__cvta_generic_to_shared(p);
}
__device__ __forceinline__ void ldsm4(u32* r, u32 a) {
    asm volatile("ldmatrix.sync.aligned.m8n8.x4.shared.b16 {%0,%1,%2,%3}, [%4];\n"
                 : "=r"(r[0]), "=r"(r[1]), "=r"(r[2]), "=r"(r[3]) : "r"(a));
}
__device__ __forceinline__ void mma16816(float* d, const u32* a, u32 b0, u32 b1) {
    asm volatile(
        "mma.sync.aligned.m16n8k16.row.col.f32.f16.f16.f32 "
        "{%0,%1,%2,%3},{%4,%5,%6,%7},{%8,%9},{%0,%1,%2,%3};\n"
        : "+f"(d[0]), "+f"(d[1]), "+f"(d[2]), "+f"(d[3])
        : "r"(a[0]), "r"(a[1]), "r"(a[2]), "r"(a[3]), "r"(b0), "r"(b1));
}
// fp16-accumulator HMMA: d[0] = half2 rows lr (n0,n0+1); d[1] = rows lr+8
__device__ __forceinline__ void mma16816_h(u32* d, const u32* a, u32 b0, u32 b1) {
    asm volatile(
        "mma.sync.aligned.m16n8k16.row.col.f16.f16.f16.f16 "
        "{%0,%1},{%2,%3,%4,%5},{%6,%7},{%0,%1};\n"
        : "+r"(d[0]), "+r"(d[1])
        : "r"(a[0]), "r"(a[1]), "r"(a[2]), "r"(a[3]), "r"(b0), "r"(b1));
}
__device__ __forceinline__ u32 ex2_h2(u32 arg) {
    u32 r;
    asm("ex2.approx.f16x2 %0, %1;" : "=r"(r) : "r"(arg));
    return r;
}
#define CP16(dst, src) asm volatile("cp.async.cg.shared.global [%0], [%1], 16;\n" :: "r"(dst), "l"(src))
#define CPCOMMIT()     asm volatile("cp.async.commit_group;\n")
#define CPWAIT(n)      asm volatile("cp.async.wait_group %0;\n" :: "n"(n))

// ----------------------- merged fp32->fp16 split of all 5 inputs + zero g_sum -----------------------
#define SPL_N0 (M_ROWS * DIN_ / 4)
#define SPL_N1 (SPL_N0 + QK_COLS * DIN_ / 4)
#define SPL_N2 (SPL_N1 + QK_COLS * DIN_ / 4)
#define SPL_N3 (SPL_N2 + V_COLS * DIN_ / 4)
#define SPL_N4 (SPL_N3 + V_COLS * V_COLS / 4)
#define SPL_N5 (SPL_N4 + NZ * C_LEN / 4)
__global__ void __launch_bounds__(256) split_all(
    const float* __restrict__ x, const float* __restrict__ mq,
    const float* __restrict__ mk, const float* __restrict__ mv,
    const float* __restrict__ wo)
{
    int i = blockIdx.x * 256 + threadIdx.x;
    if (i >= SPL_N5) return;
    if (i >= SPL_N4) {
        int j = (i - SPL_N4) * 4;
        float4 z; z.x = 0.f; z.y = 0.f; z.z = 0.f; z.w = 0.f;
        *(float4*)&g_sum[j] = z;
        return;
    }
    const float* s; __half* d; int off;
    if (i < SPL_N0)      { s = x;  d = g_xs_h; off = i; }
    else if (i < SPL_N1) { s = mq; d = g_wq_h; off = i - SPL_N0; }
    else if (i < SPL_N2) { s = mk; d = g_wk_h; off = i - SPL_N1; }
    else if (i < SPL_N3) { s = mv; d = g_wv_h; off = i - SPL_N2; }
    else                 { s = wo; d = g_wo_h; off = i - SPL_N3; }
    float4 v = ((const float4*)s)[off];
    __half2 a; a.x = __float2half_rn(v.x); a.y = __float2half_rn(v.y);
    __half2 b; b.x = __float2half_rn(v.z); b.y = __float2half_rn(v.w);
    uint2 hh; hh.x = *(u32*)&a; hh.y = *(u32*)&b;
    ((uint2*)d)[off] = hh;
}

// ---------------------------------------------------------------------------
// fp16 NT GEMM: C = A@B^T. BM=128, BN=128, BK=32. 256 thr = 8 warps (4m x 2n).
// cp.async double buffer, one __syncthreads per chunk.
// MODE 0: f32 acc, fp32 out = acc*cscale + bias.
// MODE 1: f32 acc, fp16 out = acc*cscale (+bias if non-null).
// MODE 2: f16 acc, E = exp((acc+mask[q])/8) -> fp16 out + colsums of stored E.
// MODE 3: f16 acc, fp16 out = acc + bias.
// ---------------------------------------------------------------------------
#define STG (128 * 40)     // u16 per tile: 32 data + 8 pad per row (80B stride)
#define STGB (STG * 2)
template <int MODE, int MINB>
__global__ void __launch_bounds__(256, MINB) gemm_h2(
    const __half* __restrict__ Ah, const __half* __restrict__ Bh,
    const float* __restrict__ bias, const float* __restrict__ mask, float cscale,
    float* __restrict__ Cf, __half* __restrict__ Ch,
    int K, int lda, int ldb, int ldc,
    size_t sA, size_t sB, size_t sC)
{
    __shared__ __align__(16) u16 sAs[2][STG];
    __shared__ __align__(16) u16 sBs[2][STG];

    const int tid = threadIdx.x;
    const int lane = tid & 31, wid = tid >> 5;
    const int wm = wid & 3, wn = wid >> 2;
    const int bm = blockIdx.y * 128, bn = blockIdx.x * 128;
    const int z = blockIdx.z;

    Ah += sA * z; Bh += sB * z;
    if (Cf) Cf += sC * z;
    if (Ch) Ch += sC * z;

    const int r0 = tid >> 2, c0i = (tid & 3) * 8;
    const int r1 = 64 + (tid >> 2);
    const size_t aoff0 = (size_t)(bm + r0) * lda + c0i;
    const size_t aoff1 = (size_t)(bm + r1) * lda + c0i;
    const size_t boff0 = (size_t)(bn + r0) * ldb + c0i;
    const size_t boff1 = (size_t)(bn + r1) * ldb + c0i;
    const u32 dA0 = smem_u32(&sAs[0][r0 * 40 + c0i]);
    const u32 dA1 = smem_u32(&sAs[0][r1 * 40 + c0i]);
    const u32 dB0 = smem_u32(&sBs[0][r0 * 40 + c0i]);
    const u32 dB1 = smem_u32(&sBs[0][r1 * 40 + c0i]);

    const int grp = lane >> 3, l8 = lane & 7;
    const int amr = ((grp & 1) << 3) + l8, amc = (grp >> 1) << 3;
    const int bmr = ((grp >> 1) << 3) + l8, bmc = (grp & 1) << 3;
    u32 aH_ad[2], bH_ad[4];
#pragma unroll
    for (int mi = 0; mi < 2; mi++)
        aH_ad[mi] = smem_u32(&sAs[0][(wm * 32 + mi * 16 + amr) * 40 + amc]);
#pragma unroll
    for (int p = 0; p < 4; p++)
        bH_ad[p] = smem_u32(&sBs[0][(wn * 64 + p * 16 + bmr) * 40 + bmc]);

    constexpr bool HACC = (MODE >= 2);
    float accf[2][8][4];
    u32   acch[2][8][2];
    if constexpr (HACC) {
#pragma unroll
        for (int a = 0; a < 2; a++)
#pragma unroll
            for (int b = 0; b < 8; b++) { acch[a][b][0] = 0u; acch[a][b][1] = 0u; }
    } else {
#pragma unroll
        for (int a = 0; a < 2; a++)
#pragma unroll
            for (int b = 0; b < 8; b++)
#pragma unroll
                for (int d = 0; d < 4; d++) accf[a][b][d] = 0.f;
    }

    const int NC = K >> 5;

    auto stage = [&](int buf, int c) {
        const u32 so = buf * STGB;
        const size_t k0 = (size_t)c << 5;
        CP16(dA0 + so, Ah + aoff0 + k0);
        CP16(dA1 + so, Ah + aoff1 + k0);
        CP16(dB0 + so, Bh + boff0 + k0);
        CP16(dB1 + so, Bh + boff1 + k0);
    };

    stage(0, 0); CPCOMMIT();

    for (int c = 0; c < NC; ++c) {
        const int buf = c & 1;
        CPWAIT(0);
        __syncthreads();
        if (c + 1 < NC) { stage(buf ^ 1, c + 1); CPCOMMIT(); }

        const u32 so = buf * STGB;
#pragma unroll
        for (int s = 0; s < 2; s++) {
            const u32 ko = so + s * 32;
            u32 aH[2][4], bH[4][4];
            ldsm4(aH[0], aH_ad[0] + ko);
            ldsm4(aH[1], aH_ad[1] + ko);
#pragma unroll
            for (int p = 0; p < 4; p++)
                ldsm4(bH[p], bH_ad[p] + ko);
#pragma unroll
            for (int mi = 0; mi < 2; mi++)
#pragma unroll
                for (int ni = 0; ni < 8; ni++) {
                    const int p = ni >> 1, q = (ni & 1) * 2;
                    if constexpr (HACC)
                        mma16816_h(acch[mi][ni], aH[mi], bH[p][q], bH[p][q + 1]);
                    else
                        mma16816(accf[mi][ni], aH[mi], bH[p][q], bH[p][q + 1]);
                }
        }
    }

    // ----------------- epilogue -----------------
    const float K2E = 0.18033688011112042f;   // log2(e)/8
    const int lr = lane >> 2, lc2 = (lane & 3) * 2;
#pragma unroll
    for (int mi = 0; mi < 2; mi++) {
        const int m0 = bm + wm * 32 + mi * 16 + lr;
        __half2 mk0h, mk8h;
        if (MODE == 2) {
            const float* mrow = mask + (size_t)(z >> 3) * C_LEN;
            mk0h = __float2half2_rn(mrow[m0] * K2E);
            mk8h = __float2half2_rn(mrow[m0 + 8] * K2E);
        }
#pragma unroll
        for (int ni = 0; ni < 8; ni++) {
            const int n0 = bn + wn * 64 + ni * 8 + lc2;
            if (MODE == 0) {
                float c0 = accf[mi][ni][0], c1 = accf[mi][ni][1];
                float c2 = accf[mi][ni][2], c3 = accf[mi][ni][3];
                float b0 = bias[n0], b1 = bias[n0 + 1];
                float2 o0; o0.x = c0 * cscale + b0; o0.y = c1 * cscale + b1;
                float2 o1; o1.x = c2 * cscale + b0; o1.y = c3 * cscale + b1;
                *(float2*)(Cf + (size_t)m0 * ldc + n0) = o0;
                *(float2*)(Cf + (size_t)(m0 + 8) * ldc + n0) = o1;
            } else if (MODE == 1) {
                float c0 = accf[mi][ni][0], c1 = accf[mi][ni][1];
                float c2 = accf[mi][ni][2], c3 = accf[mi][ni][3];
                float b0 = 0.f, b1 = 0.f;
                if (bias) { b0 = bias[n0]; b1 = bias[n0 + 1]; }
                __half2 p0, p1;
                p0.x = __float2half_rn(c0 * cscale + b0);
                p0.y = __float2half_rn(c1 * cscale + b1);
                p1.x = __float2half_rn(c2 * cscale + b0);
                p1.y = __float2half_rn(c3 * cscale + b1);
                *(u32*)(Ch + (size_t)m0 * ldc + n0) = *(u32*)&p0;
                *(u32*)(Ch + (size_t)(m0 + 8) * ldc + n0) = *(u32*)&p1;
            } else if (MODE == 3) {
                __half2 b2 = __floats2half2_rn(bias[n0], bias[n0 + 1]);
                __half2 o0 = __hadd2(*(__half2*)&acch[mi][ni][0], b2);
                __half2 o1 = __hadd2(*(__half2*)&acch[mi][ni][1], b2);
                *(u32*)(Ch + (size_t)m0 * ldc + n0) = *(u32*)&o0;
                *(u32*)(Ch + (size_t)(m0 + 8) * ldc + n0) = *(u32*)&o1;
            } else { // MODE 2: half2 exp2 + store + colsums of stored values
                const __half2 k2e2 = __float2half2_rn(K2E);
                __half2 s0 = *(__half2*)&acch[mi][ni][0];
                __half2 s1 = *(__half2*)&acch[mi][ni][1];
                __half2 a0 = __hfma2(s0, k2e2, mk0h);
                __half2 a1 = __hfma2(s1, k2e2, mk8h);
                u32 e0 = ex2_h2(*(u32*)&a0);
                u32 e1 = ex2_h2(*(u32*)&a1);
                *(u32*)(Ch + (size_t)m0 * ldc + n0) = e0;
                *(u32*)(Ch + (size_t)(m0 + 8) * ldc + n0) = e1;
                __half2 sums = __hadd2(*(__half2*)&e0, *(__half2*)&e1);
                float c0 = __low2float(sums), c1 = __high2float(sums);
                c0 += __shfl_xor_sync(0xffffffffu, c0, 4);
                c0 += __shfl_xor_sync(0xffffffffu, c0, 8);
                c0 += __shfl_xor_sync(0xffffffffu, c0, 16);
                c1 += __shfl_xor_sync(0xffffffffu, c1, 4);
                c1 += __shfl_xor_sync(0xffffffffu, c1, 8);
                c1 += __shfl_xor_sync(0xffffffffu, c1, 16);
                if (lane < 4) {
                    atomicAdd(&g_sum[z * C_LEN + n0], c0);
                    atomicAdd(&g_sum[z * C_LEN + n0 + 1], c1);
                }
            }
        }
    }
}

// ------- V'' transpose+scale: vt[z][d][k] = V[z][k][d] * 2048 / sum[z][k] -------
__global__ void __launch_bounds__(256) scale_v()
{
    __shared__ float t[32][33];
    const int z = blockIdx.z;
    const int k0 = blockIdx.x * 32, d0 = blockIdx.y * 32;
    const int tx = threadIdx.x & 31, ty = threadIdx.x >> 5;
    const size_t vbase = (size_t)z * (C_LEN * DV_);
#pragma unroll
    for (int i = 0; i < 4; i++)
        t[ty + i * 8][tx] = __half2float(
            g_v_h[vbase + (size_t)(k0 + ty + i * 8) * DV_ + d0 + tx]);
    __syncthreads();
    const float iv = 2048.0f / g_sum[z * C_LEN + k0 + tx];
#pragma unroll
    for (int i = 0; i < 4; i++) {
        float val = t[tx][ty + i * 8] * iv;
        size_t o = vbase + (size_t)(d0 + ty + i * 8) * C_LEN + k0 + tx;
        g_vt_h[o] = __float2half_rn(val);
    }
}

// ---------------------------------------------------------------------------
extern "C" void kernel_launch(void* const* d_in, const int* in_sizes, int n_in,
                              void* d_out, int out_size)
{
    const float* x    = (const float*)d_in[0];
    const float* mask = (const float*)d_in[1];
    const float* Mq_w = (const float*)d_in[2];
    const float* Mq_b = (const float*)d_in[3];
    const float* Mk_w = (const float*)d_in[4];
    const float* Mk_b = (const float*)d_in[5];
    const float* Mv_w = (const float*)d_in[6];
    const float* Mv_b = (const float*)d_in[7];
    const float* Wo_w = (const float*)d_in[8];
    const float* Wo_b = (const float*)d_in[9];
    float* out = (float*)d_out;

    __half *xs_h, *wq_h, *wk_h, *wv_h, *wo_h;
    __half *q_h, *k_h, *e_h, *v_h, *vt_h, *ao_h;
    cudaGetSymbolAddress((void**)&xs_h, g_xs_h);
    cudaGetSymbolAddress((void**)&wq_h, g_wq_h);
    cudaGetSymbolAddress((void**)&wk_h, g_wk_h);
    cudaGetSymbolAddress((void**)&wv_h, g_wv_h);
    cudaGetSymbolAddress((void**)&wo_h, g_wo_h);
    cudaGetSymbolAddress((void**)&q_h,  g_q_h);
    cudaGetSymbolAddress((void**)&k_h,  g_k_h);
    cudaGetSymbolAddress((void**)&e_h,  g_e_h);
    cudaGetSymbolAddress((void**)&v_h,  g_v_h);
    cudaGetSymbolAddress((void**)&vt_h, g_vt_h);
    cudaGetSymbolAddress((void**)&ao_h, g_ao_h);

    dim3 blk(256);

    // all fp32->fp16 conversions + g_sum zeroing in one launch
    split_all<<<(SPL_N5 + 255) / 256, blk>>>(x, Mq_w, Mk_w, Mv_w, Wo_w);

    // Q, K projections -> fp16 (f16 accumulators)
    gemm_h2<3, 3><<<dim3(QK_COLS / 128, M_ROWS / 128, 1), blk>>>(
        xs_h, wq_h, Mq_b, nullptr, 1.0f, nullptr, q_h,
        DIN_, DIN_, DIN_, QK_COLS, 0, 0, 0);
    gemm_h2<3, 3><<<dim3(QK_COLS / 128, M_ROWS / 128, 1), blk>>>(
        xs_h, wk_h, Mk_b, nullptr, 1.0f, nullptr, k_h,
        DIN_, DIN_, DIN_, QK_COLS, 0, 0, 0);
    // V projection -> fp16 (f32 acc)
    gemm_h2<1, 2><<<dim3(V_COLS / 128, M_ROWS / 128, 1), blk>>>(
        xs_h, wv_h, Mv_b, nullptr, 1.0f, nullptr, v_h,
        DIN_, DIN_, DIN_, V_COLS, 0, 0, 0);

    // scores -> E = exp((QK^T+mask)/8) fp16 + column sums (f16 acc)
    gemm_h2<2, 3><<<dim3(C_LEN / 128, C_LEN / 128, NZ), blk>>>(
        q_h, k_h, nullptr, mask, 1.0f, nullptr, e_h,
        DK_, DK_, DK_, C_LEN,
        (size_t)C_LEN * DK_, (size_t)C_LEN * DK_, (size_t)C_LEN * C_LEN);

    // V'' = V*2048/sum, transposed to [z][d][k]
    scale_v<<<dim3(C_LEN / 32, DV_ / 32, NZ), blk>>>();

    // AO = (E @ V''^T) / 2048  (f32 acc)
    gemm_h2<1, 2><<<dim3(DV_ / 128, C_LEN / 128, NZ), blk>>>(
        e_h, vt_h, nullptr, nullptr, 1.0f / 2048.0f, nullptr, ao_h,
        C_LEN, C_LEN, C_LEN, DV_,
        (size_t)C_LEN * C_LEN, (size_t)C_LEN * DV_, (size_t)C_LEN * DV_);

    // out projection -> d_out fp32 (f32 acc)
    gemm_h2<0, 2><<<dim3(V_COLS / 128, M_ROWS / 128, 1), blk>>>(
        ao_h, wo_h, Wo_b, nullptr, 1.0f, out, nullptr,
        V_COLS, V_COLS, V_COLS, V_COLS, 0, 0, 0);
}

// round 13
// speedup vs baseline: 6.9949x; 1.0776x over previous
#include <cuda_runtime.h>
#include <cuda_fp16.h>
#include <cstdint>

#define B_SZ   4
#define C_LEN  2048
#define H_N    8
#define DK_    64
#define DV_    128
#define DIN_   1024
#define QK_COLS 512
#define V_COLS  1024
#define M_ROWS  8192
#define NZ      32

typedef unsigned int u32;
typedef unsigned short u16;

// ----------------------- device scratch (no allocs) -----------------------
__device__ __align__(16) __half g_xs_h[M_ROWS * DIN_];
__device__ __align__(16) __half g_wq_h[QK_COLS * DIN_];
__device__ __align__(16) __half g_wk_h[QK_COLS * DIN_];
__device__ __align__(16) __half g_wv_h[V_COLS * DIN_];
__device__ __align__(16) __half g_wo_h[V_COLS * V_COLS];
__device__ __align__(16) __half g_q_h[M_ROWS * QK_COLS];
__device__ __align__(16) __half g_k_h[M_ROWS * QK_COLS];
__device__ __align__(16) __half g_e_h[(size_t)NZ * C_LEN * C_LEN];  // 256MB
__device__ __align__(16) __half g_v_h[M_ROWS * V_COLS];
__device__ __align__(16) __half g_vt_h[M_ROWS * V_COLS];
__device__ __align__(16) __half g_ao_h[M_ROWS * V_COLS];
__device__ __align__(16) float g_sum[NZ * C_LEN];

// ----------------------- helpers -----------------------
__device__ __forceinline__ u32 smem_u32(const void* p) {
    return (u32)__cvta_generic_to_shared(p);
}
__device__ __forceinline__ void ldsm4(u32* r, u32 a) {
    asm volatile("ldmatrix.sync.aligned.m8n8.x4.shared.b16 {%0,%1,%2,%3}, [%4];\n"
                 : "=r"(r[0]), "=r"(r[1]), "=r"(r[2]), "=r"(r[3]) : "r"(a));
}
__device__ __forceinline__ void mma16816(float* d, const u32* a, u32 b0, u32 b1) {
    asm volatile(
        "mma.sync.aligned.m16n8k16.row.col.f32.f16.f16.f32 "
        "{%0,%1,%2,%3},{%4,%5,%6,%7},{%8,%9},{%0,%1,%2,%3};\n"
        : "+f"(d[0]), "+f"(d[1]), "+f"(d[2]), "+f"(d[3])
        : "r"(a[0]), "r"(a[1]), "r"(a[2]), "r"(a[3]), "r"(b0), "r"(b1));
}
__device__ __forceinline__ void mma16816_h(u32* d, const u32* a, u32 b0, u32 b1) {
    asm volatile(
        "mma.sync.aligned.m16n8k16.row.col.f16.f16.f16.f16 "
        "{%0,%1},{%2,%3,%4,%5},{%6,%7},{%0,%1};\n"
        : "+r"(d[0]), "+r"(d[1])
        : "r"(a[0]), "r"(a[1]), "r"(a[2]), "r"(a[3]), "r"(b0), "r"(b1));
}
__device__ __forceinline__ u32 ex2_h2(u32 arg) {
    u32 r;
    asm("ex2.approx.f16x2 %0, %1;" : "=r"(r) : "r"(arg));
    return r;
}
#define CP16(dst, src) asm volatile("cp.async.cg.shared.global [%0], [%1], 16;\n" :: "r"(dst), "l"(src))
#define CPCOMMIT()     asm volatile("cp.async.commit_group;\n")
#define CPWAIT(n)      asm volatile("cp.async.wait_group %0;\n" :: "n"(n))

// ----------------------- merged fp32->fp16 split of all 5 inputs + zero g_sum -----------------------
#define SPL_N0 (M_ROWS * DIN_ / 4)
#define SPL_N1 (SPL_N0 + QK_COLS * DIN_ / 4)
#define SPL_N2 (SPL_N1 + QK_COLS * DIN_ / 4)
#define SPL_N3 (SPL_N2 + V_COLS * DIN_ / 4)
#define SPL_N4 (SPL_N3 + V_COLS * V_COLS / 4)
#define SPL_N5 (SPL_N4 + NZ * C_LEN / 4)
__global__ void __launch_bounds__(256) split_all(
    const float* __restrict__ x, const float* __restrict__ mq,
    const float* __restrict__ mk, const float* __restrict__ mv,
    const float* __restrict__ wo)
{
    int i = blockIdx.x * 256 + threadIdx.x;
    if (i >= SPL_N5) return;
    if (i >= SPL_N4) {
        int j = (i - SPL_N4) * 4;
        float4 z; z.x = 0.f; z.y = 0.f; z.z = 0.f; z.w = 0.f;
        *(float4*)&g_sum[j] = z;
        return;
    }
    const float* s; __half* d; int off;
    if (i < SPL_N0)      { s = x;  d = g_xs_h; off = i; }
    else if (i < SPL_N1) { s = mq; d = g_wq_h; off = i - SPL_N0; }
    else if (i < SPL_N2) { s = mk; d = g_wk_h; off = i - SPL_N1; }
    else if (i < SPL_N3) { s = mv; d = g_wv_h; off = i - SPL_N2; }
    else                 { s = wo; d = g_wo_h; off = i - SPL_N3; }
    float4 v = ((const float4*)s)[off];
    __half2 a; a.x = __float2half_rn(v.x); a.y = __float2half_rn(v.y);
    __half2 b; b.x = __float2half_rn(v.z); b.y = __float2half_rn(v.w);
    uint2 hh; hh.x = *(u32*)&a; hh.y = *(u32*)&b;
    ((uint2*)d)[off] = hh;
}

// ---------------------------------------------------------------------------
// fp16 NT GEMM: C = A@B^T. BM=128, BN=128, BK=32. 256 thr = 8 warps (4m x 2n).
// 4-stage cp.async pipeline (3 chunks of lead > DRAM latency), dynamic smem.
// MODE 0: f32 acc, fp32 out = acc*cscale + bias.
// MODE 1: f32 acc, fp16 out = acc*cscale (+bias if non-null).
// MODE 2: f16 acc, E = exp((acc+mask[q])/8) -> fp16 out + colsums of stored E.
// MODE 3: f16 acc, fp16 out = acc + bias.
// ---------------------------------------------------------------------------
#define NSTAGE 4
#define STG (128 * 40)                 // u16 per tile stage (80B row stride)
#define TILEB (STG * 2)                // 10240 bytes per tile stage
#define SMEM_DYN (NSTAGE * TILEB * 2)  // 81920 bytes total (A + B regions)
template <int MODE>
__global__ void __launch_bounds__(256, 2) gemm_h2(
    const __half* __restrict__ Ah, const __half* __restrict__ Bh,
    const float* __restrict__ bias, const float* __restrict__ mask, float cscale,
    float* __restrict__ Cf, __half* __restrict__ Ch,
    int K, int lda, int ldb, int ldc,
    size_t sA, size_t sB, size_t sC)
{
    extern __shared__ __align__(16) u16 dyns[];
    u16* sA0 = dyns;                       // NSTAGE stages of A
    u16* sB0 = dyns + NSTAGE * STG;        // NSTAGE stages of B

    const int tid = threadIdx.x;
    const int lane = tid & 31, wid = tid >> 5;
    const int wm = wid & 3, wn = wid >> 2;
    const int bm = blockIdx.y * 128, bn = blockIdx.x * 128;
    const int z = blockIdx.z;

    Ah += sA * z; Bh += sB * z;
    if (Cf) Cf += sC * z;
    if (Ch) Ch += sC * z;

    const int r0 = tid >> 2, c0i = (tid & 3) * 8;
    const int r1 = 64 + (tid >> 2);
    const size_t aoff0 = (size_t)(bm + r0) * lda + c0i;
    const size_t aoff1 = (size_t)(bm + r1) * lda + c0i;
    const size_t boff0 = (size_t)(bn + r0) * ldb + c0i;
    const size_t boff1 = (size_t)(bn + r1) * ldb + c0i;
    const u32 dA0 = smem_u32(&sA0[r0 * 40 + c0i]);
    const u32 dA1 = smem_u32(&sA0[r1 * 40 + c0i]);
    const u32 dB0 = smem_u32(&sB0[r0 * 40 + c0i]);
    const u32 dB1 = smem_u32(&sB0[r1 * 40 + c0i]);

    const int grp = lane >> 3, l8 = lane & 7;
    const int amr = ((grp & 1) << 3) + l8, amc = (grp >> 1) << 3;
    const int bmr = ((grp >> 1) << 3) + l8, bmc = (grp & 1) << 3;
    u32 aH_ad[2], bH_ad[4];
#pragma unroll
    for (int mi = 0; mi < 2; mi++)
        aH_ad[mi] = smem_u32(&sA0[(wm * 32 + mi * 16 + amr) * 40 + amc]);
#pragma unroll
    for (int p = 0; p < 4; p++)
        bH_ad[p] = smem_u32(&sB0[(wn * 64 + p * 16 + bmr) * 40 + bmc]);

    constexpr bool HACC = (MODE >= 2);
    float accf[2][8][4];
    u32   acch[2][8][2];
    if constexpr (HACC) {
#pragma unroll
        for (int a = 0; a < 2; a++)
#pragma unroll
            for (int b = 0; b < 8; b++) { acch[a][b][0] = 0u; acch[a][b][1] = 0u; }
    } else {
#pragma unroll
        for (int a = 0; a < 2; a++)
#pragma unroll
            for (int b = 0; b < 8; b++)
#pragma unroll
                for (int d = 0; d < 4; d++) accf[a][b][d] = 0.f;
    }

    const int NC = K >> 5;

    auto stage = [&](int buf, int c) {
        const u32 so = buf * TILEB;
        const size_t k0 = (size_t)c << 5;
        CP16(dA0 + so, Ah + aoff0 + k0);
        CP16(dA1 + so, Ah + aoff1 + k0);
        CP16(dB0 + so, Bh + boff0 + k0);
        CP16(dB1 + so, Bh + boff1 + k0);
    };

    // prologue: stage up to NSTAGE-1 chunks; always commit (empty groups keep
    // the outstanding-group count invariant so CPWAIT(NSTAGE-2) waits for the
    // oldest real chunk)
#pragma unroll
    for (int s = 0; s < NSTAGE - 1; ++s) {
        if (s < NC) stage(s, s);
        CPCOMMIT();
    }

    for (int c = 0; c < NC; ++c) {
        const int buf = c & (NSTAGE - 1);
        CPWAIT(NSTAGE - 2);   // chunk c landed
        __syncthreads();      // all warps: chunk c visible, chunk c-1 consumed
        {
            const int cn = c + NSTAGE - 1;
            if (cn < NC) stage(cn & (NSTAGE - 1), cn);
            CPCOMMIT();
        }

        const u32 so = buf * TILEB;
#pragma unroll
        for (int s = 0; s < 2; s++) {
            const u32 ko = so + s * 32;
            u32 aH[2][4], bH[4][4];
            ldsm4(aH[0], aH_ad[0] + ko);
            ldsm4(aH[1], aH_ad[1] + ko);
#pragma unroll
            for (int p = 0; p < 4; p++)
                ldsm4(bH[p], bH_ad[p] + ko);
#pragma unroll
            for (int mi = 0; mi < 2; mi++)
#pragma unroll
                for (int ni = 0; ni < 8; ni++) {
                    const int p = ni >> 1, q = (ni & 1) * 2;
                    if constexpr (HACC)
                        mma16816_h(acch[mi][ni], aH[mi], bH[p][q], bH[p][q + 1]);
                    else
                        mma16816(accf[mi][ni], aH[mi], bH[p][q], bH[p][q + 1]);
                }
        }
    }

    // ----------------- epilogue -----------------
    const float K2E = 0.18033688011112042f;   // log2(e)/8
    const int lr = lane >> 2, lc2 = (lane & 3) * 2;
#pragma unroll
    for (int mi = 0; mi < 2; mi++) {
        const int m0 = bm + wm * 32 + mi * 16 + lr;
        __half2 mk0h, mk8h;
        if (MODE == 2) {
            const float* mrow = mask + (size_t)(z >> 3) * C_LEN;
            mk0h = __float2half2_rn(mrow[m0] * K2E);
            mk8h = __float2half2_rn(mrow[m0 + 8] * K2E);
        }
#pragma unroll
        for (int ni = 0; ni < 8; ni++) {
            const int n0 = bn + wn * 64 + ni * 8 + lc2;
            if (MODE == 0) {
                float c0 = accf[mi][ni][0], c1 = accf[mi][ni][1];
                float c2 = accf[mi][ni][2], c3 = accf[mi][ni][3];
                float b0 = bias[n0], b1 = bias[n0 + 1];
                float2 o0; o0.x = c0 * cscale + b0; o0.y = c1 * cscale + b1;
                float2 o1; o1.x = c2 * cscale + b0; o1.y = c3 * cscale + b1;
                *(float2*)(Cf + (size_t)m0 * ldc + n0) = o0;
                *(float2*)(Cf + (size_t)(m0 + 8) * ldc + n0) = o1;
            } else if (MODE == 1) {
                float c0 = accf[mi][ni][0], c1 = accf[mi][ni][1];
                float c2 = accf[mi][ni][2], c3 = accf[mi][ni][3];
                float b0 = 0.f, b1 = 0.f;
                if (bias) { b0 = bias[n0]; b1 = bias[n0 + 1]; }
                __half2 p0, p1;
                p0.x = __float2half_rn(c0 * cscale + b0);
                p0.y = __float2half_rn(c1 * cscale + b1);
                p1.x = __float2half_rn(c2 * cscale + b0);
                p1.y = __float2half_rn(c3 * cscale + b1);
                *(u32*)(Ch + (size_t)m0 * ldc + n0) = *(u32*)&p0;
                *(u32*)(Ch + (size_t)(m0 + 8) * ldc + n0) = *(u32*)&p1;
            } else if (MODE == 3) {
                __half2 b2 = __floats2half2_rn(bias[n0], bias[n0 + 1]);
                __half2 o0 = __hadd2(*(__half2*)&acch[mi][ni][0], b2);
                __half2 o1 = __hadd2(*(__half2*)&acch[mi][ni][1], b2);
                *(u32*)(Ch + (size_t)m0 * ldc + n0) = *(u32*)&o0;
                *(u32*)(Ch + (size_t)(m0 + 8) * ldc + n0) = *(u32*)&o1;
            } else { // MODE 2: half2 exp2 + store + colsums of stored values
                const __half2 k2e2 = __float2half2_rn(K2E);
                __half2 s0 = *(__half2*)&acch[mi][ni][0];
                __half2 s1 = *(__half2*)&acch[mi][ni][1];
                __half2 a0 = __hfma2(s0, k2e2, mk0h);
                __half2 a1 = __hfma2(s1, k2e2, mk8h);
                u32 e0 = ex2_h2(*(u32*)&a0);
                u32 e1 = ex2_h2(*(u32*)&a1);
                *(u32*)(Ch + (size_t)m0 * ldc + n0) = e0;
                *(u32*)(Ch + (size_t)(m0 + 8) * ldc + n0) = e1;
                __half2 sums = __hadd2(*(__half2*)&e0, *(__half2*)&e1);
                float c0 = __low2float(sums), c1 = __high2float(sums);
                c0 += __shfl_xor_sync(0xffffffffu, c0, 4);
                c0 += __shfl_xor_sync(0xffffffffu, c0, 8);
                c0 += __shfl_xor_sync(0xffffffffu, c0, 16);
                c1 += __shfl_xor_sync(0xffffffffu, c1, 4);
                c1 += __shfl_xor_sync(0xffffffffu, c1, 8);
                c1 += __shfl_xor_sync(0xffffffffu, c1, 16);
                if (lane < 4) {
                    atomicAdd(&g_sum[z * C_LEN + n0], c0);
                    atomicAdd(&g_sum[z * C_LEN + n0 + 1], c1);
                }
            }
        }
    }
}

// ------- V'' transpose+scale: vt[z][d][k] = V[z][k][d] * 2048 / sum[z][k] -------
__global__ void __launch_bounds__(256) scale_v()
{
    __shared__ float t[32][33];
    const int z = blockIdx.z;
    const int k0 = blockIdx.x * 32, d0 = blockIdx.y * 32;
    const int tx = threadIdx.x & 31, ty = threadIdx.x >> 5;
    const size_t vbase = (size_t)z * (C_LEN * DV_);
#pragma unroll
    for (int i = 0; i < 4; i++)
        t[ty + i * 8][tx] = __half2float(
            g_v_h[vbase + (size_t)(k0 + ty + i * 8) * DV_ + d0 + tx]);
    __syncthreads();
    const float iv = 2048.0f / g_sum[z * C_LEN + k0 + tx];
#pragma unroll
    for (int i = 0; i < 4; i++) {
        float val = t[tx][ty + i * 8] * iv;
        size_t o = vbase + (size_t)(d0 + ty + i * 8) * C_LEN + k0 + tx;
        g_vt_h[o] = __float2half_rn(val);
    }
}

// ---------------------------------------------------------------------------
extern "C" void kernel_launch(void* const* d_in, const int* in_sizes, int n_in,
                              void* d_out, int out_size)
{
    const float* x    = (const float*)d_in[0];
    const float* mask = (const float*)d_in[1];
    const float* Mq_w = (const float*)d_in[2];
    const float* Mq_b = (const float*)d_in[3];
    const float* Mk_w = (const float*)d_in[4];
    const float* Mk_b = (const float*)d_in[5];
    const float* Mv_w = (const float*)d_in[6];
    const float* Mv_b = (const float*)d_in[7];
    const float* Wo_w = (const float*)d_in[8];
    const float* Wo_b = (const float*)d_in[9];
    float* out = (float*)d_out;

    __half *xs_h, *wq_h, *wk_h, *wv_h, *wo_h;
    __half *q_h, *k_h, *e_h, *v_h, *vt_h, *ao_h;
    cudaGetSymbolAddress((void**)&xs_h, g_xs_h);
    cudaGetSymbolAddress((void**)&wq_h, g_wq_h);
    cudaGetSymbolAddress((void**)&wk_h, g_wk_h);
    cudaGetSymbolAddress((void**)&wv_h, g_wv_h);
    cudaGetSymbolAddress((void**)&wo_h, g_wo_h);
    cudaGetSymbolAddress((void**)&q_h,  g_q_h);
    cudaGetSymbolAddress((void**)&k_h,  g_k_h);
    cudaGetSymbolAddress((void**)&e_h,  g_e_h);
    cudaGetSymbolAddress((void**)&v_h,  g_v_h);
    cudaGetSymbolAddress((void**)&vt_h, g_vt_h);
    cudaGetSymbolAddress((void**)&ao_h, g_ao_h);

    // >48KB dynamic smem opt-in (host-side attribute, graph-capture safe)
    cudaFuncSetAttribute(gemm_h2<0>, cudaFuncAttributeMaxDynamicSharedMemorySize, SMEM_DYN);
    cudaFuncSetAttribute(gemm_h2<1>, cudaFuncAttributeMaxDynamicSharedMemorySize, SMEM_DYN);
    cudaFuncSetAttribute(gemm_h2<2>, cudaFuncAttributeMaxDynamicSharedMemorySize, SMEM_DYN);
    cudaFuncSetAttribute(gemm_h2<3>, cudaFuncAttributeMaxDynamicSharedMemorySize, SMEM_DYN);

    dim3 blk(256);

    // all fp32->fp16 conversions + g_sum zeroing in one launch
    split_all<<<(SPL_N5 + 255) / 256, blk>>>(x, Mq_w, Mk_w, Mv_w, Wo_w);

    // Q, K projections -> fp16 (f16 accumulators)
    gemm_h2<3><<<dim3(QK_COLS / 128, M_ROWS / 128, 1), blk, SMEM_DYN>>>(
        xs_h, wq_h, Mq_b, nullptr, 1.0f, nullptr, q_h,
        DIN_, DIN_, DIN_, QK_COLS, 0, 0, 0);
    gemm_h2<3><<<dim3(QK_COLS / 128, M_ROWS / 128, 1), blk, SMEM_DYN>>>(
        xs_h, wk_h, Mk_b, nullptr, 1.0f, nullptr, k_h,
        DIN_, DIN_, DIN_, QK_COLS, 0, 0, 0);
    // V projection -> fp16 (f32 acc)
    gemm_h2<1><<<dim3(V_COLS / 128, M_ROWS / 128, 1), blk, SMEM_DYN>>>(
        xs_h, wv_h, Mv_b, nullptr, 1.0f, nullptr, v_h,
        DIN_, DIN_, DIN_, V_COLS, 0, 0, 0);

    // scores -> E = exp((QK^T+mask)/8) fp16 + column sums (f16 acc)
    gemm_h2<2><<<dim3(C_LEN / 128, C_LEN / 128, NZ), blk, SMEM_DYN>>>(
        q_h, k_h, nullptr, mask, 1.0f, nullptr, e_h,
        DK_, DK_, DK_, C_LEN,
        (size_t)C_LEN * DK_, (size_t)C_LEN * DK_, (size_t)C_LEN * C_LEN);

    // V'' = V*2048/sum, transposed to [z][d][k]
    scale_v<<<dim3(C_LEN / 32, DV_ / 32, NZ), blk>>>();

    // AO = (E @ V''^T) / 2048  (f32 acc)
    gemm_h2<1><<<dim3(DV_ / 128, C_LEN / 128, NZ), blk, SMEM_DYN>>>(
        e_h, vt_h, nullptr, nullptr, 1.0f / 2048.0f, nullptr, ao_h,
        C_LEN, C_LEN, C_LEN, DV_,
        (size_t)C_LEN * C_LEN, (size_t)C_LEN * DV_, (size_t)C_LEN * DV_);

    // out projection -> d_out fp32 (f32 acc)
    gemm_h2<0><<<dim3(V_COLS / 128, M_ROWS / 128, 1), blk, SMEM_DYN>>>(
        ao_h, wo_h, Wo_b, nullptr, 1.0f, out, nullptr,
        V_COLS, V_COLS, V_COLS, V_COLS, 0, 0, 0);
}